// round 13
// baseline (speedup 1.0000x reference)
#include <cuda_runtime.h>
#include <mma.h>

using namespace nvcuda;

// ---------------------------------------------------------------------------
// HGTransformerLayer — tf32 tensor-core, round 13.
//   k[b,n] = Kbase[n] + KE[t], v[b,n] = Vbase[n] + VE[t]  (t in {0,1})
//   scores = Q·Kbase^T + qe[row][t];  out = P·Vbase + w0·VE0 + w1·VE1
// GEMMs: smem-staged 32x64; QKV 1xTF32, proj 3xTF32.
// Attention: n split into two 512-halves (no-max softmax => halves combine
// linearly), S buffer halved -> 73KB smem -> 3 CTAs/SM, 24 warps.
// ---------------------------------------------------------------------------

#define SCALE_Q 0.17677669529663687f  // 1/sqrt(32)

__device__ float g_Q[1024 * 256];   // [h][b][32], scaled, tf32-rounded
__device__ float g_K[1024 * 256];   // [h][n][32], tf32-rounded
__device__ float g_V[1024 * 256];   // [h][n][32], tf32-rounded
__device__ float g_KE[2 * 256];
__device__ float g_VE[2 * 256];
__device__ float g_AO[1024 * 256];  // row-major [b][256]
__device__ unsigned g_mba2[1024 * 32];  // adjacency bits: [row][n/32]
__device__ unsigned g_mbt2[1024 * 32];  // edge-type bits

typedef wmma::fragment<wmma::matrix_a, 16, 16, 8, wmma::precision::tf32, wmma::row_major> FragA;
typedef wmma::fragment<wmma::matrix_b, 16, 16, 8, wmma::precision::tf32, wmma::col_major> FragBc;
typedef wmma::fragment<wmma::matrix_b, 16, 16, 8, wmma::precision::tf32, wmma::row_major> FragBr;
typedef wmma::fragment<wmma::accumulator, 16, 16, 8, float> FragC;

template <typename F>
__device__ __forceinline__ void to_tf32(F& f) {
#pragma unroll
    for (int i = 0; i < f.num_elements; ++i) f.x[i] = wmma::__float_to_tf32(f.x[i]);
}
template <typename F>
__device__ __forceinline__ void split_tf32(const F& raw, F& hi, F& lo) {
#pragma unroll
    for (int i = 0; i < raw.num_elements; ++i) {
        float h = wmma::__float_to_tf32(raw.x[i]);
        hi.x[i] = h;
        lo.x[i] = wmma::__float_to_tf32(raw.x[i] - h);
    }
}

// ---------------------------------------------------------------------------
// GEMM body: C[32x64 tile] = (A[.,256] @ W[256,256]^T + bias) * scale
// ACC3: 3xTF32; else single tf32 pass. 256 thr, warp tile 16x16, smem dbuf.
// ---------------------------------------------------------------------------
template <bool ACC3>
__device__ __forceinline__ void gemm_body(const float* __restrict__ A,
                                          const float* __restrict__ W,
                                          const float* __restrict__ bias,
                                          float* __restrict__ C, float scale,
                                          bool headmode, int m0, int n0)
{
    __shared__ float sA[2][32 * 20];
    __shared__ float sB[2][64 * 20];
    __shared__ float sEp[8 * 320];

    const int tid = threadIdx.x;
    const int warp = tid >> 5;
    const int wr = warp >> 2;
    const int wc = warp & 3;

    float4 pa, pb;
    if (tid < 128)
        pa = *reinterpret_cast<const float4*>(&A[(m0 + (tid >> 2)) * 256 + (tid & 3) * 4]);
    pb = *reinterpret_cast<const float4*>(&W[(n0 + (tid >> 2)) * 256 + (tid & 3) * 4]);

    FragC c;
    wmma::fill_fragment(c, 0.f);

    for (int s = 0; s < 16; ++s) {
        float* bufA = sA[s & 1];
        float* bufB = sB[s & 1];
        if (tid < 128)
            *reinterpret_cast<float4*>(&bufA[(tid >> 2) * 20 + (tid & 3) * 4]) = pa;
        *reinterpret_cast<float4*>(&bufB[(tid >> 2) * 20 + (tid & 3) * 4]) = pb;
        __syncthreads();
        if (s < 15) {
            int k0 = (s + 1) * 16;
            if (tid < 128)
                pa = *reinterpret_cast<const float4*>(&A[(m0 + (tid >> 2)) * 256 + k0 + (tid & 3) * 4]);
            pb = *reinterpret_cast<const float4*>(&W[(n0 + (tid >> 2)) * 256 + k0 + (tid & 3) * 4]);
        }
#pragma unroll
        for (int kt = 0; kt < 2; ++kt) {
            FragA araw;
            FragBc braw;
            wmma::load_matrix_sync(araw, &bufA[wr * 16 * 20 + kt * 8], 20);
            wmma::load_matrix_sync(braw, &bufB[wc * 16 * 20 + kt * 8], 20);
            if (ACC3) {
                FragA ahi, alo;
                FragBc bhi, blo;
                split_tf32(araw, ahi, alo);
                split_tf32(braw, bhi, blo);
                wmma::mma_sync(c, ahi, bhi, c);
                wmma::mma_sync(c, ahi, blo, c);
                wmma::mma_sync(c, alo, bhi, c);
            } else {
                to_tf32(araw);
                to_tf32(braw);
                wmma::mma_sync(c, araw, braw, c);
            }
        }
    }
    __syncthreads();
    wmma::store_matrix_sync(&sEp[warp * 320], c, 20, wmma::mem_row_major);
    __syncthreads();

#pragma unroll
    for (int i = 0; i < 8; ++i) {
        int o = tid + i * 256;
        int lm = o >> 6, ln = o & 63;
        int wsrc = (lm >> 4) * 4 + (ln >> 4);
        float val = sEp[wsrc * 320 + (lm & 15) * 20 + (ln & 15)];
        int m = m0 + lm, n = n0 + ln;
        val = (val + __ldg(&bias[n])) * scale;
        if (headmode) {
            val = wmma::__float_to_tf32(val);
            C[(n >> 5) * 32768 + m * 32 + (n & 31)] = val;
        } else {
            C[m * 256 + n] = val;
        }
    }
}

// ---------------------------------------------------------------------------
// prep: [0,128) mask pack; [128,512) qkv GEMMs (1xTF32); [512,516) edge proj.
// ---------------------------------------------------------------------------
__global__ __launch_bounds__(256)
void prep_kernel(const float* __restrict__ hT, const float* __restrict__ hN,
                 const float* __restrict__ Wq, const float* __restrict__ bq,
                 const float* __restrict__ Wk, const float* __restrict__ bk,
                 const float* __restrict__ Wv, const float* __restrict__ bv,
                 const float* __restrict__ E,
                 const int* __restrict__ adj, const int* __restrict__ et)
{
    const int b = blockIdx.x;
    if (b < 128) {
        const int gw = b * 256 + threadIdx.x;
        const int4* ap = reinterpret_cast<const int4*>(adj) + gw * 8;
        const int4* tp = reinterpret_cast<const int4*>(et) + gw * 8;
        unsigned va = 0, vt = 0;
#pragma unroll
        for (int i = 0; i < 8; ++i) {
            int4 xa = __ldg(ap + i);
            int4 xt = __ldg(tp + i);
            va |= (unsigned)(xa.x != 0) << (i * 4 + 0);
            va |= (unsigned)(xa.y != 0) << (i * 4 + 1);
            va |= (unsigned)(xa.z != 0) << (i * 4 + 2);
            va |= (unsigned)(xa.w != 0) << (i * 4 + 3);
            vt |= (unsigned)(xt.x != 0) << (i * 4 + 0);
            vt |= (unsigned)(xt.y != 0) << (i * 4 + 1);
            vt |= (unsigned)(xt.z != 0) << (i * 4 + 2);
            vt |= (unsigned)(xt.w != 0) << (i * 4 + 3);
        }
        g_mba2[gw] = va;
        g_mbt2[gw] = vt;
    } else if (b < 512) {
        const int bb = b - 128;
        const int mat = bb >> 7;
        const int m0 = (bb & 31) * 32;
        const int n0 = ((bb >> 5) & 3) * 64;
        if (mat == 0)      gemm_body<false>(hT, Wq, bq, g_Q, SCALE_Q, true, m0, n0);
        else if (mat == 1) gemm_body<false>(hN, Wk, bk, g_K, 1.f, true, m0, n0);
        else               gemm_body<false>(hN, Wv, bv, g_V, 1.f, true, m0, n0);
    } else {
        const int bb = b - 512;
        const int t = bb & 1;
        const int isv = bb >> 1;
        const float* W = isv ? Wv : Wk;
        float* out = isv ? g_VE : g_KE;
        __shared__ float e[256];
        e[threadIdx.x] = E[t * 256 + threadIdx.x];
        __syncthreads();
        const int warp = threadIdx.x >> 5, lane = threadIdx.x & 31;
        for (int d = warp; d < 256; d += 8) {
            float acc = 0.f;
            for (int k = lane; k < 256; k += 32) acc += e[k] * W[d * 256 + k];
#pragma unroll
            for (int m = 16; m; m >>= 1) acc += __shfl_xor_sync(0xffffffffu, acc, m);
            if (lane == 0) out[t * 256 + d] = acc;
        }
    }
}

__global__ __launch_bounds__(256)
void proj_kernel(const float* __restrict__ Wo, const float* __restrict__ bo,
                 float* __restrict__ out)
{
    gemm_body<true>(g_AO, Wo, bo, out, 1.f, false, blockIdx.x * 32, blockIdx.y * 64);
}

// ---------------------------------------------------------------------------
// Attention: grid (64 rowblocks, 8 heads), 256 thr / 8 warps, 3 CTAs/SM.
// 16 rows/CTA; n processed in two 512-halves (no-max softmax => linear
// combination). S[16x520] smem; K/V in 128-kv double-buffered chunks.
// ---------------------------------------------------------------------------
#define SS_LD2 520
#define CH_F (128 * 36)
#define SMEM_ATTN_F (16 * SS_LD2 + 2 * CH_F + 16 * 36 + 32 + 64 + 16 + 16)  // 18240 f

__global__ __launch_bounds__(256, 3)
void attn_kernel()
{
    extern __shared__ float sm[];
    float* sS  = sm;                          // 8320
    float* sKV = sS + 16 * SS_LD2;            // 9216 (dbuf; later AV reduce)
    float* sQ  = sKV + 2 * CH_F;              // 576
    float* sqe = sQ + 16 * 36;                // 32
    float* sVE = sqe + 32;                    // 64
    float* srs = sVE + 64;                    // 16
    float* srw = srs + 16;                    // 16

    const int tid = threadIdx.x;
    const int h = blockIdx.y;
    const int b0 = blockIdx.x * 16;
    const int w = tid >> 5;
    const int row = tid >> 4, c16 = tid & 15;

    // ---- stage Q, VE ----
#pragma unroll
    for (int j = 0; j < 2; ++j) {
        int idx = tid + j * 256;
        sQ[(idx >> 5) * 36 + (idx & 31)] = g_Q[h * 32768 + (b0 + (idx >> 5)) * 32 + (idx & 31)];
    }
    if (tid < 64) sVE[tid] = g_VE[(tid >> 5) * 256 + h * 32 + (tid & 31)];
    __syncthreads();

    // qe[row][t] = Q[row].KE[t]  (visible to softmax via score-phase syncs)
    if (tid < 32) {
        int rr = tid >> 1, t = tid & 1;
        float a = 0.f;
#pragma unroll
        for (int d = 0; d < 32; ++d) a += sQ[rr * 36 + d] * g_KE[t * 256 + h * 32 + d];
        sqe[rr * 2 + t] = a;
    }

    // ---- Q fragments (pre-rounded tf32) ----
    FragA af[4];
#pragma unroll
    for (int kt = 0; kt < 4; ++kt)
        wmma::load_matrix_sync(af[kt], &sQ[kt * 8], 36);

    FragC oc0, oc1;
    wmma::fill_fragment(oc0, 0.f);
    wmma::fill_fragment(oc1, 0.f);
    float rs = 0.f, rw = 0.f;

    const float4* gKh = reinterpret_cast<const float4*>(g_K + h * 32768);
    const float4* gVh = reinterpret_cast<const float4*>(g_V + h * 32768);

    // prefetch K half0 chunk0
    float4 pf0 = __ldg(gKh + tid);
    float4 pf1 = __ldg(gKh + tid + 256);
    float4 pf2 = __ldg(gKh + tid + 512);
    float4 pf3 = __ldg(gKh + tid + 768);

#pragma unroll 1
    for (int nh = 0; nh < 2; ++nh) {
        const float4* gKb = gKh + nh * 4096;   // 512 kv * 32 f = 4096 float4
        const float4* gVb = gVh + nh * 4096;

        // ---- SCORE: 4 chunks of 128 kv ----
        for (int kc = 0; kc < 4; ++kc) {
            float* buf = sKV + (kc & 1) * CH_F;
            {
                int i0 = tid, i1 = tid + 256, i2 = tid + 512, i3 = tid + 768;
                *reinterpret_cast<float4*>(&buf[(i0 >> 3) * 36 + (i0 & 7) * 4]) = pf0;
                *reinterpret_cast<float4*>(&buf[(i1 >> 3) * 36 + (i1 & 7) * 4]) = pf1;
                *reinterpret_cast<float4*>(&buf[(i2 >> 3) * 36 + (i2 & 7) * 4]) = pf2;
                *reinterpret_cast<float4*>(&buf[(i3 >> 3) * 36 + (i3 & 7) * 4]) = pf3;
            }
            __syncthreads();
            {
                const float4* src = (kc < 3) ? (gKb + (kc + 1) * 1024) : gVb;
                pf0 = __ldg(src + tid);
                pf1 = __ldg(src + tid + 256);
                pf2 = __ldg(src + tid + 512);
                pf3 = __ldg(src + tid + 768);
            }
            FragC c0;
            wmma::fill_fragment(c0, 0.f);
#pragma unroll
            for (int kt = 0; kt < 4; ++kt) {
                FragBc bf;
                wmma::load_matrix_sync(bf, &buf[w * 16 * 36 + kt * 8], 36);
                wmma::mma_sync(c0, af[kt], bf, c0);
            }
            wmma::store_matrix_sync(&sS[kc * 128 + w * 16], c0, SS_LD2, wmma::mem_row_major);
            // no trailing sync (double-buffered)
        }
        __syncthreads();   // S complete; sKV settled

        // ---- softmax on this half (one mask word per thread) ----
        {
            const unsigned a = __ldg(&g_mba2[(b0 + row) * 32 + nh * 16 + c16]);
            const unsigned t = __ldg(&g_mbt2[(b0 + row) * 32 + nh * 16 + c16]);
            const float qe0 = sqe[row * 2], qe1 = sqe[row * 2 + 1];
            float* rowp = sS + row * SS_LD2 + c16 * 32;
#pragma unroll
            for (int jj = 0; jj < 8; ++jj) {
                int j = (jj + c16) & 7;       // lane stagger
                float4 s = *reinterpret_cast<float4*>(&rowp[j * 4]);
                int bb = j * 4;
                float p0 = ((a >> (bb + 0)) & 1u) ? __expf(s.x + (((t >> (bb + 0)) & 1u) ? qe1 : qe0)) : 0.f;
                float p1 = ((a >> (bb + 1)) & 1u) ? __expf(s.y + (((t >> (bb + 1)) & 1u) ? qe1 : qe0)) : 0.f;
                float p2 = ((a >> (bb + 2)) & 1u) ? __expf(s.z + (((t >> (bb + 2)) & 1u) ? qe1 : qe0)) : 0.f;
                float p3 = ((a >> (bb + 3)) & 1u) ? __expf(s.w + (((t >> (bb + 3)) & 1u) ? qe1 : qe0)) : 0.f;
                rs += p0 + p1 + p2 + p3;
                if ((t >> (bb + 0)) & 1u) rw += p0;
                if ((t >> (bb + 1)) & 1u) rw += p1;
                if ((t >> (bb + 2)) & 1u) rw += p2;
                if ((t >> (bb + 3)) & 1u) rw += p3;
                s.x = wmma::__float_to_tf32(p0);
                s.y = wmma::__float_to_tf32(p1);
                s.z = wmma::__float_to_tf32(p2);
                s.w = wmma::__float_to_tf32(p3);
                *reinterpret_cast<float4*>(&rowp[j * 4]) = s;
            }
        }
        __syncthreads();   // P complete before cross-warp AV reads

        // ---- AV: 4 chunks of V; warp w owns kv slice [w*16,+16) per chunk ----
        for (int kc = 0; kc < 4; ++kc) {
            float* buf = sKV + (kc & 1) * CH_F;
            {
                int i0 = tid, i1 = tid + 256, i2 = tid + 512, i3 = tid + 768;
                *reinterpret_cast<float4*>(&buf[(i0 >> 3) * 36 + (i0 & 7) * 4]) = pf0;
                *reinterpret_cast<float4*>(&buf[(i1 >> 3) * 36 + (i1 & 7) * 4]) = pf1;
                *reinterpret_cast<float4*>(&buf[(i2 >> 3) * 36 + (i2 & 7) * 4]) = pf2;
                *reinterpret_cast<float4*>(&buf[(i3 >> 3) * 36 + (i3 & 7) * 4]) = pf3;
            }
            __syncthreads();
            if (kc < 3 || nh == 0) {
                const float4* src = (kc < 3) ? (gVb + (kc + 1) * 1024) : (gKh + 4096);
                pf0 = __ldg(src + tid);
                pf1 = __ldg(src + tid + 256);
                pf2 = __ldg(src + tid + 512);
                pf3 = __ldg(src + tid + 768);
            }
#pragma unroll
            for (int kt2 = 0; kt2 < 2; ++kt2) {
                int kb = w * 16 + kt2 * 8;
                FragA pa;
                wmma::load_matrix_sync(pa, &sS[kc * 128 + kb], SS_LD2);
                FragBr vb0, vb1;
                wmma::load_matrix_sync(vb0, &buf[kb * 36 + 0], 36);
                wmma::load_matrix_sync(vb1, &buf[kb * 36 + 16], 36);
                wmma::mma_sync(oc0, pa, vb0, oc0);
                wmma::mma_sync(oc1, pa, vb1, oc1);
            }
            // no trailing sync (double-buffered)
        }
        __syncthreads();   // all AV reads done before sS/sKV reused
    }

    // ---- row sums (16-lane reduce) ----
#pragma unroll
    for (int m = 8; m; m >>= 1) {
        rs += __shfl_xor_sync(0xffffffffu, rs, m);
        rw += __shfl_xor_sync(0xffffffffu, rw, m);
    }
    if (c16 == 0) { srs[row] = rs; srw[row] = rw; }

    // ---- reduce 8 warp-partials through buf0 (safe: trailing sync above) ----
    float* red = sKV;   // 8 * 576 = 4608 = CH_F
    wmma::store_matrix_sync(&red[w * 576 + 0],  oc0, 36, wmma::mem_row_major);
    wmma::store_matrix_sync(&red[w * 576 + 16], oc1, 36, wmma::mem_row_major);
    __syncthreads();

#pragma unroll
    for (int i = 0; i < 2; ++i) {
        int o = tid + i * 256;
        int r = o >> 5, d = o & 31;
        float v = 0.f;
#pragma unroll
        for (int ww = 0; ww < 8; ++ww) v += red[ww * 576 + r * 36 + d];
        float st = srs[r], w1s = srw[r];
        float inv = st > 0.f ? 1.f / st : 0.f;
        v = v * inv + (st - w1s) * inv * sVE[d] + w1s * inv * sVE[32 + d];
        g_AO[(b0 + r) * 256 + h * 32 + d] = v;
    }
}

// ---------------------------------------------------------------------------
extern "C" void kernel_launch(void* const* d_in, const int* in_sizes, int n_in,
                              void* d_out, int out_size)
{
    const float* h_target = (const float*)d_in[0];
    const float* h_neigh  = (const float*)d_in[1];
    const int*   adjacency = (const int*)d_in[2];
    const int*   edge_types = (const int*)d_in[3];
    const float* Wq = (const float*)d_in[4];
    const float* bq = (const float*)d_in[5];
    const float* Wk = (const float*)d_in[6];
    const float* bk = (const float*)d_in[7];
    const float* Wv = (const float*)d_in[8];
    const float* bv = (const float*)d_in[9];
    const float* Wo = (const float*)d_in[10];
    const float* bo = (const float*)d_in[11];
    const float* E  = (const float*)d_in[12];
    float* out = (float*)d_out;

    const int attn_smem = SMEM_ATTN_F * 4;   // 72,960 B -> 3 CTAs/SM
    static int smem_set = 0;
    if (!smem_set) {
        cudaFuncSetAttribute(attn_kernel, cudaFuncAttributeMaxDynamicSharedMemorySize,
                             attn_smem);
        smem_set = 1;
    }

    prep_kernel<<<516, 256>>>(h_target, h_neigh, Wq, bq, Wk, bk, Wv, bv, E,
                              adjacency, edge_types);
    attn_kernel<<<dim3(64, 8), 256, attn_smem>>>();
    proj_kernel<<<dim3(32, 4), 256>>>(Wo, bo, out);
}

// round 14
// speedup vs baseline: 1.2755x; 1.2755x over previous
#include <cuda_runtime.h>
#include <mma.h>

using namespace nvcuda;

// ---------------------------------------------------------------------------
// HGTransformerLayer — tf32 tensor-core, round 14.
//   k[b,n] = Kbase[n] + KE[t], v[b,n] = Vbase[n] + VE[t]  (t in {0,1})
//   scores = Q·Kbase^T + qe[row][t];  out = P·Vbase + w0·VE0 + w1·VE1
// GEMMs: 16x64 tiles / 128 threads (high residency); QKV 1xTF32, proj 3xTF32.
// Attention: R12 design verbatim (best known: 16 rows/CTA, 2 CTAs/SM,
// single-pass no-max softmax, double-buffered K/V chunks).
// ---------------------------------------------------------------------------

#define SCALE_Q 0.17677669529663687f  // 1/sqrt(32)

__device__ float g_Q[1024 * 256];   // [h][b][32], scaled, tf32-rounded
__device__ float g_K[1024 * 256];   // [h][n][32], tf32-rounded
__device__ float g_V[1024 * 256];   // [h][n][32], tf32-rounded
__device__ float g_KE[2 * 256];
__device__ float g_VE[2 * 256];
__device__ float g_AO[1024 * 256];  // row-major [b][256]
__device__ unsigned g_mba2[1024 * 32];  // adjacency bits: [row][n/32]
__device__ unsigned g_mbt2[1024 * 32];  // edge-type bits

typedef wmma::fragment<wmma::matrix_a, 16, 16, 8, wmma::precision::tf32, wmma::row_major> FragA;
typedef wmma::fragment<wmma::matrix_b, 16, 16, 8, wmma::precision::tf32, wmma::col_major> FragBc;
typedef wmma::fragment<wmma::matrix_b, 16, 16, 8, wmma::precision::tf32, wmma::row_major> FragBr;
typedef wmma::fragment<wmma::accumulator, 16, 16, 8, float> FragC;

template <typename F>
__device__ __forceinline__ void to_tf32(F& f) {
#pragma unroll
    for (int i = 0; i < f.num_elements; ++i) f.x[i] = wmma::__float_to_tf32(f.x[i]);
}
template <typename F>
__device__ __forceinline__ void split_tf32(const F& raw, F& hi, F& lo) {
#pragma unroll
    for (int i = 0; i < raw.num_elements; ++i) {
        float h = wmma::__float_to_tf32(raw.x[i]);
        hi.x[i] = h;
        lo.x[i] = wmma::__float_to_tf32(raw.x[i] - h);
    }
}

// ---------------------------------------------------------------------------
// GEMM body: C[16x64 tile] = (A[.,256] @ W[256,256]^T + bias) * scale
// 128 threads / 4 warps (warp = col tile), warp tile 16x16, BK=16, smem dbuf.
// ACC3: 3xTF32; else single tf32 pass.
// ---------------------------------------------------------------------------
template <bool ACC3>
__device__ __forceinline__ void gemm16_body(const float* __restrict__ A,
                                            const float* __restrict__ W,
                                            const float* __restrict__ bias,
                                            float* __restrict__ C, float scale,
                                            bool headmode, int m0, int n0)
{
    __shared__ float sA[2][16 * 20];
    __shared__ float sB[2][64 * 20];
    __shared__ float sEp[4 * 320];

    const int tid = threadIdx.x;
    const int warp = tid >> 5;       // 0..3 = col tile

    float4 pa, pb0, pb1;
    if (tid < 64)
        pa = *reinterpret_cast<const float4*>(&A[(m0 + (tid >> 2)) * 256 + (tid & 3) * 4]);
    pb0 = *reinterpret_cast<const float4*>(&W[(n0 + (tid >> 2)) * 256 + (tid & 3) * 4]);
    pb1 = *reinterpret_cast<const float4*>(&W[(n0 + 32 + (tid >> 2)) * 256 + (tid & 3) * 4]);

    FragC c;
    wmma::fill_fragment(c, 0.f);

    for (int s = 0; s < 16; ++s) {
        float* bufA = sA[s & 1];
        float* bufB = sB[s & 1];
        if (tid < 64)
            *reinterpret_cast<float4*>(&bufA[(tid >> 2) * 20 + (tid & 3) * 4]) = pa;
        *reinterpret_cast<float4*>(&bufB[(tid >> 2) * 20 + (tid & 3) * 4]) = pb0;
        *reinterpret_cast<float4*>(&bufB[(32 + (tid >> 2)) * 20 + (tid & 3) * 4]) = pb1;
        __syncthreads();
        if (s < 15) {
            int k0 = (s + 1) * 16;
            if (tid < 64)
                pa = *reinterpret_cast<const float4*>(&A[(m0 + (tid >> 2)) * 256 + k0 + (tid & 3) * 4]);
            pb0 = *reinterpret_cast<const float4*>(&W[(n0 + (tid >> 2)) * 256 + k0 + (tid & 3) * 4]);
            pb1 = *reinterpret_cast<const float4*>(&W[(n0 + 32 + (tid >> 2)) * 256 + k0 + (tid & 3) * 4]);
        }
#pragma unroll
        for (int kt = 0; kt < 2; ++kt) {
            FragA araw;
            FragBc braw;
            wmma::load_matrix_sync(araw, &bufA[kt * 8], 20);
            wmma::load_matrix_sync(braw, &bufB[warp * 16 * 20 + kt * 8], 20);
            if (ACC3) {
                FragA ahi, alo;
                FragBc bhi, blo;
                split_tf32(araw, ahi, alo);
                split_tf32(braw, bhi, blo);
                wmma::mma_sync(c, ahi, bhi, c);
                wmma::mma_sync(c, ahi, blo, c);
                wmma::mma_sync(c, alo, bhi, c);
            } else {
                to_tf32(araw);
                to_tf32(braw);
                wmma::mma_sync(c, araw, braw, c);
            }
        }
        // no trailing sync: next iteration writes the other buffer
    }
    __syncthreads();
    wmma::store_matrix_sync(&sEp[warp * 320], c, 20, wmma::mem_row_major);
    __syncthreads();

#pragma unroll
    for (int i = 0; i < 8; ++i) {
        int o = tid + i * 128;               // 1024 outputs, 16x64 tile
        int lm = o >> 6, ln = o & 63;
        int wsrc = ln >> 4;
        float val = sEp[wsrc * 320 + lm * 20 + (ln & 15)];
        int m = m0 + lm, n = n0 + ln;
        val = (val + __ldg(&bias[n])) * scale;
        if (headmode) {
            val = wmma::__float_to_tf32(val);   // pre-rounded for attn MMAs
            C[(n >> 5) * 32768 + m * 32 + (n & 31)] = val;
        } else {
            C[m * 256 + n] = val;
        }
    }
}

// ---------------------------------------------------------------------------
// prep (128-thread blocks): [0,256) mask pack; [256,1024) qkv GEMMs (1xTF32);
// [1024,1028) edge projections.
// ---------------------------------------------------------------------------
__global__ __launch_bounds__(128)
void prep_kernel(const float* __restrict__ hT, const float* __restrict__ hN,
                 const float* __restrict__ Wq, const float* __restrict__ bq,
                 const float* __restrict__ Wk, const float* __restrict__ bk,
                 const float* __restrict__ Wv, const float* __restrict__ bv,
                 const float* __restrict__ E,
                 const int* __restrict__ adj, const int* __restrict__ et)
{
    const int b = blockIdx.x;
    if (b < 256) {
        const int gw = b * 128 + threadIdx.x;       // word index 0..32767
        const int4* ap = reinterpret_cast<const int4*>(adj) + gw * 8;
        const int4* tp = reinterpret_cast<const int4*>(et) + gw * 8;
        unsigned va = 0, vt = 0;
#pragma unroll
        for (int i = 0; i < 8; ++i) {
            int4 xa = __ldg(ap + i);
            int4 xt = __ldg(tp + i);
            va |= (unsigned)(xa.x != 0) << (i * 4 + 0);
            va |= (unsigned)(xa.y != 0) << (i * 4 + 1);
            va |= (unsigned)(xa.z != 0) << (i * 4 + 2);
            va |= (unsigned)(xa.w != 0) << (i * 4 + 3);
            vt |= (unsigned)(xt.x != 0) << (i * 4 + 0);
            vt |= (unsigned)(xt.y != 0) << (i * 4 + 1);
            vt |= (unsigned)(xt.z != 0) << (i * 4 + 2);
            vt |= (unsigned)(xt.w != 0) << (i * 4 + 3);
        }
        g_mba2[gw] = va;
        g_mbt2[gw] = vt;
    } else if (b < 1024) {
        const int bb = b - 256;                 // 0..767
        const int mat = bb >> 8;                // 0..2
        const int idx = bb & 255;
        const int m0 = (idx & 63) * 16;
        const int n0 = (idx >> 6) * 64;
        if (mat == 0)      gemm16_body<false>(hT, Wq, bq, g_Q, SCALE_Q, true, m0, n0);
        else if (mat == 1) gemm16_body<false>(hN, Wk, bk, g_K, 1.f, true, m0, n0);
        else               gemm16_body<false>(hN, Wv, bv, g_V, 1.f, true, m0, n0);
    } else {
        const int bb = b - 1024;
        const int t = bb & 1;
        const int isv = bb >> 1;
        const float* W = isv ? Wv : Wk;
        float* out = isv ? g_VE : g_KE;
        __shared__ float e[256];
        e[threadIdx.x] = E[t * 256 + threadIdx.x];
        e[threadIdx.x + 128] = E[t * 256 + threadIdx.x + 128];
        __syncthreads();
        const int warp = threadIdx.x >> 5, lane = threadIdx.x & 31;
        for (int d = warp; d < 256; d += 4) {
            float acc = 0.f;
            for (int k = lane; k < 256; k += 32) acc += e[k] * W[d * 256 + k];
#pragma unroll
            for (int m = 16; m; m >>= 1) acc += __shfl_xor_sync(0xffffffffu, acc, m);
            if (lane == 0) out[t * 256 + d] = acc;
        }
    }
}

__global__ __launch_bounds__(128)
void proj_kernel(const float* __restrict__ Wo, const float* __restrict__ bo,
                 float* __restrict__ out)
{
    gemm16_body<true>(g_AO, Wo, bo, out, 1.f, false, blockIdx.x * 16, blockIdx.y * 64);
}

// ---------------------------------------------------------------------------
// Attention (R12 verbatim): grid (64 rowblocks, 8 heads), 256 thr, 2 CTAs/SM.
// 16 rows/CTA. S[16x1032] smem; K/V 128-kv double-buffered chunks.
// Softmax: single pass (no max), P tf32-rounded on write.
// ---------------------------------------------------------------------------
#define SS_LD 1032
#define CH_F (128 * 36)
#define SMEM_ATTN_F (16 * SS_LD + 2 * CH_F + 16 * 36 + 32 + 64 + 16 + 16 + 1024)

__global__ __launch_bounds__(256, 2)
void attn_kernel()
{
    extern __shared__ float sm[];
    float* sS  = sm;                          // 16512
    float* sKV = sS + 16 * SS_LD;             // 9216 (dbuf; later AV reduce)
    float* sQ  = sKV + 2 * CH_F;              // 576
    float* sqe = sQ + 16 * 36;                // 32
    float* sVE = sqe + 32;                    // 64
    float* srs = sVE + 64;                    // 16
    float* srw = srs + 16;                    // 16
    unsigned* sAdj = (unsigned*)(srw + 16);   // 512
    unsigned* sTyp = sAdj + 512;              // 512

    const int tid = threadIdx.x;
    const int h = blockIdx.y;
    const int b0 = blockIdx.x * 16;
    const int w = tid >> 5;

    // ---- stage Q, masks, VE ----
#pragma unroll
    for (int j = 0; j < 2; ++j) {
        int idx = tid + j * 256;
        sQ[(idx >> 5) * 36 + (idx & 31)] = g_Q[h * 32768 + (b0 + (idx >> 5)) * 32 + (idx & 31)];
    }
#pragma unroll
    for (int j = 0; j < 2; ++j) {
        int idx = tid + j * 256;
        sAdj[idx] = g_mba2[(b0 + (idx >> 5)) * 32 + (idx & 31)];
        sTyp[idx] = g_mbt2[(b0 + (idx >> 5)) * 32 + (idx & 31)];
    }
    if (tid < 64) sVE[tid] = g_VE[(tid >> 5) * 256 + h * 32 + (tid & 31)];
    __syncthreads();

    // qe[row][t] = Q[row].KE[t]
    if (tid < 32) {
        int row = tid >> 1, t = tid & 1;
        float a = 0.f;
#pragma unroll
        for (int d = 0; d < 32; ++d) a += sQ[row * 36 + d] * g_KE[t * 256 + h * 32 + d];
        sqe[row * 2 + t] = a;
    }

    // ---- Q fragments (pre-rounded tf32) ----
    FragA af[4];
#pragma unroll
    for (int kt = 0; kt < 4; ++kt)
        wmma::load_matrix_sync(af[kt], &sQ[kt * 8], 36);

    // ---- SCORE: stream K chunks (dbuf -> one sync per chunk) ----
    const float4* gK = reinterpret_cast<const float4*>(g_K + h * 32768);
    float4 pf0, pf1, pf2, pf3;
    pf0 = __ldg(gK + tid);
    pf1 = __ldg(gK + tid + 256);
    pf2 = __ldg(gK + tid + 512);
    pf3 = __ldg(gK + tid + 768);

    for (int kc = 0; kc < 8; ++kc) {
        float* buf = sKV + (kc & 1) * CH_F;
        {
            int i0 = tid, i1 = tid + 256, i2 = tid + 512, i3 = tid + 768;
            *reinterpret_cast<float4*>(&buf[(i0 >> 3) * 36 + (i0 & 7) * 4]) = pf0;
            *reinterpret_cast<float4*>(&buf[(i1 >> 3) * 36 + (i1 & 7) * 4]) = pf1;
            *reinterpret_cast<float4*>(&buf[(i2 >> 3) * 36 + (i2 & 7) * 4]) = pf2;
            *reinterpret_cast<float4*>(&buf[(i3 >> 3) * 36 + (i3 & 7) * 4]) = pf3;
        }
        __syncthreads();
        if (kc < 7) {
            const float4* src = gK + (kc + 1) * 1024;
            pf0 = __ldg(src + tid);
            pf1 = __ldg(src + tid + 256);
            pf2 = __ldg(src + tid + 512);
            pf3 = __ldg(src + tid + 768);
        }
        FragC c0;
        wmma::fill_fragment(c0, 0.f);
#pragma unroll
        for (int kt = 0; kt < 4; ++kt) {
            FragBc bf;
            wmma::load_matrix_sync(bf, &buf[w * 16 * 36 + kt * 8], 36);
            wmma::mma_sync(c0, af[kt], bf, c0);
        }
        wmma::store_matrix_sync(&sS[kc * 128 + w * 16], c0, SS_LD, wmma::mem_row_major);
        // no trailing sync (double-buffered)
    }
    __syncthreads();   // all S written before softmax

    // ---- V chunk 0 prefetch ----
    const float4* gV = reinterpret_cast<const float4*>(g_V + h * 32768);
    pf0 = __ldg(gV + tid);
    pf1 = __ldg(gV + tid + 256);
    pf2 = __ldg(gV + tid + 512);
    pf3 = __ldg(gV + tid + 768);

    // ---- softmax: ONE pass, no max subtraction ----
    const int row = tid >> 4, c16 = tid & 15;
    const unsigned aw0 = sAdj[row * 32 + c16 * 2 + 0];
    const unsigned aw1 = sAdj[row * 32 + c16 * 2 + 1];
    const unsigned tw0 = sTyp[row * 32 + c16 * 2 + 0];
    const unsigned tw1 = sTyp[row * 32 + c16 * 2 + 1];
    const float qe0 = sqe[row * 2], qe1 = sqe[row * 2 + 1];
    float* rowp = sS + row * SS_LD + c16 * 64;

    float rs = 0.f, rw = 0.f;
#pragma unroll
    for (int jj = 0; jj < 16; ++jj) {
        int j = (jj + c16) & 15;              // lane stagger
        float4 s = *reinterpret_cast<float4*>(&rowp[j * 4]);
        unsigned a = (j & 8) ? aw1 : aw0;
        unsigned t = (j & 8) ? tw1 : tw0;
        int bb = (j & 7) * 4;
        float p0 = ((a >> (bb + 0)) & 1u) ? __expf(s.x + (((t >> (bb + 0)) & 1u) ? qe1 : qe0)) : 0.f;
        float p1 = ((a >> (bb + 1)) & 1u) ? __expf(s.y + (((t >> (bb + 1)) & 1u) ? qe1 : qe0)) : 0.f;
        float p2 = ((a >> (bb + 2)) & 1u) ? __expf(s.z + (((t >> (bb + 2)) & 1u) ? qe1 : qe0)) : 0.f;
        float p3 = ((a >> (bb + 3)) & 1u) ? __expf(s.w + (((t >> (bb + 3)) & 1u) ? qe1 : qe0)) : 0.f;
        rs += p0 + p1 + p2 + p3;
        if ((t >> (bb + 0)) & 1u) rw += p0;
        if ((t >> (bb + 1)) & 1u) rw += p1;
        if ((t >> (bb + 2)) & 1u) rw += p2;
        if ((t >> (bb + 3)) & 1u) rw += p3;
        s.x = wmma::__float_to_tf32(p0);      // pre-round P for the PV MMA
        s.y = wmma::__float_to_tf32(p1);
        s.z = wmma::__float_to_tf32(p2);
        s.w = wmma::__float_to_tf32(p3);
        *reinterpret_cast<float4*>(&rowp[j * 4]) = s;
    }
#pragma unroll
    for (int m = 8; m; m >>= 1) {
        rs += __shfl_xor_sync(0xffffffffu, rs, m);
        rw += __shfl_xor_sync(0xffffffffu, rw, m);
    }
    if (c16 == 0) { srs[row] = rs; srw[row] = rw; }
    __syncthreads();

    // ---- AV: warp w owns kv slice [w*16, w*16+16) of each chunk ----
    FragC oc[2];
    wmma::fill_fragment(oc[0], 0.f);
    wmma::fill_fragment(oc[1], 0.f);

    for (int kc = 0; kc < 8; ++kc) {
        float* buf = sKV + (kc & 1) * CH_F;
        {
            int i0 = tid, i1 = tid + 256, i2 = tid + 512, i3 = tid + 768;
            *reinterpret_cast<float4*>(&buf[(i0 >> 3) * 36 + (i0 & 7) * 4]) = pf0;
            *reinterpret_cast<float4*>(&buf[(i1 >> 3) * 36 + (i1 & 7) * 4]) = pf1;
            *reinterpret_cast<float4*>(&buf[(i2 >> 3) * 36 + (i2 & 7) * 4]) = pf2;
            *reinterpret_cast<float4*>(&buf[(i3 >> 3) * 36 + (i3 & 7) * 4]) = pf3;
        }
        __syncthreads();
        if (kc < 7) {
            const float4* src = gV + (kc + 1) * 1024;
            pf0 = __ldg(src + tid);
            pf1 = __ldg(src + tid + 256);
            pf2 = __ldg(src + tid + 512);
            pf3 = __ldg(src + tid + 768);
        }
#pragma unroll
        for (int kt2 = 0; kt2 < 2; ++kt2) {
            int kb = w * 16 + kt2 * 8;
            FragA pa;
            wmma::load_matrix_sync(pa, &sS[kc * 128 + kb], SS_LD);
            FragBr vb0, vb1;
            wmma::load_matrix_sync(vb0, &buf[kb * 36 + 0], 36);
            wmma::load_matrix_sync(vb1, &buf[kb * 36 + 16], 36);
            wmma::mma_sync(oc[0], pa, vb0, oc[0]);
            wmma::mma_sync(oc[1], pa, vb1, oc[1]);
        }
        // no trailing sync (double-buffered; red-store safety argued below)
    }

    // red = buf0 region; last buf0 reads were chunk 6 (all warps passed
    // chunk 7's leading sync, hence finished chunk 6); chunk-7 readers use buf1.
    float* red = sKV;   // 8 * 576 = 4608 = CH_F
    wmma::store_matrix_sync(&red[w * 576 + 0],  oc[0], 36, wmma::mem_row_major);
    wmma::store_matrix_sync(&red[w * 576 + 16], oc[1], 36, wmma::mem_row_major);
    __syncthreads();

#pragma unroll
    for (int i = 0; i < 2; ++i) {
        int o = tid + i * 256;
        int r = o >> 5, d = o & 31;
        float v = 0.f;
#pragma unroll
        for (int ww = 0; ww < 8; ++ww) v += red[ww * 576 + r * 36 + d];
        float st = srs[r], w1s = srw[r];
        float inv = st > 0.f ? 1.f / st : 0.f;
        v = v * inv + (st - w1s) * inv * sVE[d] + w1s * inv * sVE[32 + d];
        g_AO[(b0 + r) * 256 + h * 32 + d] = v;
    }
}

// ---------------------------------------------------------------------------
extern "C" void kernel_launch(void* const* d_in, const int* in_sizes, int n_in,
                              void* d_out, int out_size)
{
    const float* h_target = (const float*)d_in[0];
    const float* h_neigh  = (const float*)d_in[1];
    const int*   adjacency = (const int*)d_in[2];
    const int*   edge_types = (const int*)d_in[3];
    const float* Wq = (const float*)d_in[4];
    const float* bq = (const float*)d_in[5];
    const float* Wk = (const float*)d_in[6];
    const float* bk = (const float*)d_in[7];
    const float* Wv = (const float*)d_in[8];
    const float* bv = (const float*)d_in[9];
    const float* Wo = (const float*)d_in[10];
    const float* bo = (const float*)d_in[11];
    const float* E  = (const float*)d_in[12];
    float* out = (float*)d_out;

    const int attn_smem = SMEM_ATTN_F * 4;   // 109,824 B -> 2 CTAs/SM
    static int smem_set = 0;
    if (!smem_set) {
        cudaFuncSetAttribute(attn_kernel, cudaFuncAttributeMaxDynamicSharedMemorySize,
                             attn_smem);
        smem_set = 1;
    }

    prep_kernel<<<1028, 128>>>(h_target, h_neigh, Wq, bq, Wk, bk, Wv, bv, E,
                               adjacency, edge_types);
    attn_kernel<<<dim3(64, 8), 256, attn_smem>>>();
    proj_kernel<<<dim3(64, 4), 128>>>(Wo, bo, out);
}

// round 15
// speedup vs baseline: 1.3502x; 1.0586x over previous
#include <cuda_runtime.h>
#include <mma.h>

using namespace nvcuda;

// ---------------------------------------------------------------------------
// HGTransformerLayer — tf32 tensor-core, round 15 (= R12 + 2xTF32 proj +
// persistent attention grid).
//   k[b,n] = Kbase[n] + KE[t], v[b,n] = Vbase[n] + VE[t]  (t in {0,1})
//   scores = Q·Kbase^T + qe[row][t];  out = P·Vbase + w0·VE0 + w1·VE1
// GEMMs: smem-staged 32x64; QKV 1xTF32, proj 2xTF32 (A split, W rounded).
// Attention: 16 rows/CTA, 2 CTAs/SM, persistent 296-CTA grid (no wave tail),
// single-pass no-max softmax, double-buffered K/V chunks.
// ---------------------------------------------------------------------------

#define SCALE_Q 0.17677669529663687f  // 1/sqrt(32)

__device__ float g_Q[1024 * 256];   // [h][b][32], scaled, tf32-rounded
__device__ float g_K[1024 * 256];   // [h][n][32], tf32-rounded
__device__ float g_V[1024 * 256];   // [h][n][32], tf32-rounded
__device__ float g_KE[2 * 256];
__device__ float g_VE[2 * 256];
__device__ float g_AO[1024 * 256];  // row-major [b][256]
__device__ unsigned g_mba2[1024 * 32];  // adjacency bits: [row][n/32]
__device__ unsigned g_mbt2[1024 * 32];  // edge-type bits

typedef wmma::fragment<wmma::matrix_a, 16, 16, 8, wmma::precision::tf32, wmma::row_major> FragA;
typedef wmma::fragment<wmma::matrix_b, 16, 16, 8, wmma::precision::tf32, wmma::col_major> FragBc;
typedef wmma::fragment<wmma::matrix_b, 16, 16, 8, wmma::precision::tf32, wmma::row_major> FragBr;
typedef wmma::fragment<wmma::accumulator, 16, 16, 8, float> FragC;

template <typename F>
__device__ __forceinline__ void to_tf32(F& f) {
#pragma unroll
    for (int i = 0; i < f.num_elements; ++i) f.x[i] = wmma::__float_to_tf32(f.x[i]);
}
template <typename F>
__device__ __forceinline__ void split_tf32(const F& raw, F& hi, F& lo) {
#pragma unroll
    for (int i = 0; i < raw.num_elements; ++i) {
        float h = wmma::__float_to_tf32(raw.x[i]);
        hi.x[i] = h;
        lo.x[i] = wmma::__float_to_tf32(raw.x[i] - h);
    }
}

// ---------------------------------------------------------------------------
// GEMM body: C[32x64 tile] = (A[.,256] @ W[256,256]^T + bias) * scale
// 256 threads, 8 warps (2 row x 4 col), warp tile 16x16, BK=16, smem dbuf.
// ACC2: 2xTF32 (split A only, round W); else single tf32 pass.
// ---------------------------------------------------------------------------
template <bool ACC2>
__device__ __forceinline__ void gemm_body(const float* __restrict__ A,
                                          const float* __restrict__ W,
                                          const float* __restrict__ bias,
                                          float* __restrict__ C, float scale,
                                          bool headmode, int m0, int n0)
{
    __shared__ float sA[2][32 * 20];
    __shared__ float sB[2][64 * 20];
    __shared__ float sEp[8 * 320];

    const int tid = threadIdx.x;
    const int warp = tid >> 5;
    const int wr = warp >> 2;
    const int wc = warp & 3;

    float4 pa, pb;
    if (tid < 128)
        pa = *reinterpret_cast<const float4*>(&A[(m0 + (tid >> 2)) * 256 + (tid & 3) * 4]);
    pb = *reinterpret_cast<const float4*>(&W[(n0 + (tid >> 2)) * 256 + (tid & 3) * 4]);

    FragC c;
    wmma::fill_fragment(c, 0.f);

    for (int s = 0; s < 16; ++s) {
        float* bufA = sA[s & 1];
        float* bufB = sB[s & 1];
        if (tid < 128)
            *reinterpret_cast<float4*>(&bufA[(tid >> 2) * 20 + (tid & 3) * 4]) = pa;
        *reinterpret_cast<float4*>(&bufB[(tid >> 2) * 20 + (tid & 3) * 4]) = pb;
        __syncthreads();
        if (s < 15) {
            int k0 = (s + 1) * 16;
            if (tid < 128)
                pa = *reinterpret_cast<const float4*>(&A[(m0 + (tid >> 2)) * 256 + k0 + (tid & 3) * 4]);
            pb = *reinterpret_cast<const float4*>(&W[(n0 + (tid >> 2)) * 256 + k0 + (tid & 3) * 4]);
        }
#pragma unroll
        for (int kt = 0; kt < 2; ++kt) {
            FragA araw;
            FragBc braw;
            wmma::load_matrix_sync(araw, &bufA[wr * 16 * 20 + kt * 8], 20);
            wmma::load_matrix_sync(braw, &bufB[wc * 16 * 20 + kt * 8], 20);
            if (ACC2) {
                FragA ahi, alo;
                split_tf32(araw, ahi, alo);
                to_tf32(braw);
                wmma::mma_sync(c, ahi, braw, c);
                wmma::mma_sync(c, alo, braw, c);
            } else {
                to_tf32(araw);
                to_tf32(braw);
                wmma::mma_sync(c, araw, braw, c);
            }
        }
    }
    __syncthreads();
    wmma::store_matrix_sync(&sEp[warp * 320], c, 20, wmma::mem_row_major);
    __syncthreads();

#pragma unroll
    for (int i = 0; i < 8; ++i) {
        int o = tid + i * 256;
        int lm = o >> 6, ln = o & 63;
        int wsrc = (lm >> 4) * 4 + (ln >> 4);
        float val = sEp[wsrc * 320 + (lm & 15) * 20 + (ln & 15)];
        int m = m0 + lm, n = n0 + ln;
        val = (val + __ldg(&bias[n])) * scale;
        if (headmode) {
            val = wmma::__float_to_tf32(val);
            C[(n >> 5) * 32768 + m * 32 + (n & 31)] = val;
        } else {
            C[m * 256 + n] = val;
        }
    }
}

// ---------------------------------------------------------------------------
// prep: [0,128) mask pack; [128,512) qkv GEMMs (1xTF32); [512,516) edge proj.
// ---------------------------------------------------------------------------
__global__ __launch_bounds__(256)
void prep_kernel(const float* __restrict__ hT, const float* __restrict__ hN,
                 const float* __restrict__ Wq, const float* __restrict__ bq,
                 const float* __restrict__ Wk, const float* __restrict__ bk,
                 const float* __restrict__ Wv, const float* __restrict__ bv,
                 const float* __restrict__ E,
                 const int* __restrict__ adj, const int* __restrict__ et)
{
    const int b = blockIdx.x;
    if (b < 128) {
        const int gw = b * 256 + threadIdx.x;
        const int4* ap = reinterpret_cast<const int4*>(adj) + gw * 8;
        const int4* tp = reinterpret_cast<const int4*>(et) + gw * 8;
        unsigned va = 0, vt = 0;
#pragma unroll
        for (int i = 0; i < 8; ++i) {
            int4 xa = __ldg(ap + i);
            int4 xt = __ldg(tp + i);
            va |= (unsigned)(xa.x != 0) << (i * 4 + 0);
            va |= (unsigned)(xa.y != 0) << (i * 4 + 1);
            va |= (unsigned)(xa.z != 0) << (i * 4 + 2);
            va |= (unsigned)(xa.w != 0) << (i * 4 + 3);
            vt |= (unsigned)(xt.x != 0) << (i * 4 + 0);
            vt |= (unsigned)(xt.y != 0) << (i * 4 + 1);
            vt |= (unsigned)(xt.z != 0) << (i * 4 + 2);
            vt |= (unsigned)(xt.w != 0) << (i * 4 + 3);
        }
        g_mba2[gw] = va;
        g_mbt2[gw] = vt;
    } else if (b < 512) {
        const int bb = b - 128;
        const int mat = bb >> 7;
        const int m0 = (bb & 31) * 32;
        const int n0 = ((bb >> 5) & 3) * 64;
        if (mat == 0)      gemm_body<false>(hT, Wq, bq, g_Q, SCALE_Q, true, m0, n0);
        else if (mat == 1) gemm_body<false>(hN, Wk, bk, g_K, 1.f, true, m0, n0);
        else               gemm_body<false>(hN, Wv, bv, g_V, 1.f, true, m0, n0);
    } else {
        const int bb = b - 512;
        const int t = bb & 1;
        const int isv = bb >> 1;
        const float* W = isv ? Wv : Wk;
        float* out = isv ? g_VE : g_KE;
        __shared__ float e[256];
        e[threadIdx.x] = E[t * 256 + threadIdx.x];
        __syncthreads();
        const int warp = threadIdx.x >> 5, lane = threadIdx.x & 31;
        for (int d = warp; d < 256; d += 8) {
            float acc = 0.f;
            for (int k = lane; k < 256; k += 32) acc += e[k] * W[d * 256 + k];
#pragma unroll
            for (int m = 16; m; m >>= 1) acc += __shfl_xor_sync(0xffffffffu, acc, m);
            if (lane == 0) out[t * 256 + d] = acc;
        }
    }
}

__global__ __launch_bounds__(256)
void proj_kernel(const float* __restrict__ Wo, const float* __restrict__ bo,
                 float* __restrict__ out)
{
    gemm_body<true>(g_AO, Wo, bo, out, 1.f, false, blockIdx.x * 32, blockIdx.y * 64);
}

// ---------------------------------------------------------------------------
// Attention: persistent grid of 296 CTAs (148 SM x 2), each loops over jobs
// (rowblock, head) = (job & 63, job >> 6), job in {bid, bid+296}.
// 16 rows/job. S[16x1032] smem; K/V 128-kv double-buffered chunks.
// Softmax: single pass (no max), P tf32-rounded on write.
// ---------------------------------------------------------------------------
#define SS_LD 1032
#define CH_F (128 * 36)
#define SMEM_ATTN_F (16 * SS_LD + 2 * CH_F + 16 * 36 + 32 + 64 + 16 + 16 + 1024)
#define ATTN_CTAS 296

__global__ __launch_bounds__(256, 2)
void attn_kernel()
{
    extern __shared__ float sm[];
    float* sS  = sm;                          // 16512
    float* sKV = sS + 16 * SS_LD;             // 9216 (dbuf; later AV reduce)
    float* sQ  = sKV + 2 * CH_F;              // 576
    float* sqe = sQ + 16 * 36;                // 32
    float* sVE = sqe + 32;                    // 64
    float* srs = sVE + 64;                    // 16
    float* srw = srs + 16;                    // 16
    unsigned* sAdj = (unsigned*)(srw + 16);   // 512
    unsigned* sTyp = sAdj + 512;              // 512

    const int tid = threadIdx.x;
    const int w = tid >> 5;
    const int row = tid >> 4, c16 = tid & 15;

    for (int job = blockIdx.x; job < 512; job += ATTN_CTAS) {
        const int h = job >> 6;
        const int b0 = (job & 63) * 16;

        // ---- stage Q, masks, VE ----
#pragma unroll
        for (int j = 0; j < 2; ++j) {
            int idx = tid + j * 256;
            sQ[(idx >> 5) * 36 + (idx & 31)] = g_Q[h * 32768 + (b0 + (idx >> 5)) * 32 + (idx & 31)];
        }
#pragma unroll
        for (int j = 0; j < 2; ++j) {
            int idx = tid + j * 256;
            sAdj[idx] = g_mba2[(b0 + (idx >> 5)) * 32 + (idx & 31)];
            sTyp[idx] = g_mbt2[(b0 + (idx >> 5)) * 32 + (idx & 31)];
        }
        if (tid < 64) sVE[tid] = g_VE[(tid >> 5) * 256 + h * 32 + (tid & 31)];
        __syncthreads();

        // qe[row][t] = Q[row].KE[t]
        if (tid < 32) {
            int rr = tid >> 1, t = tid & 1;
            float a = 0.f;
#pragma unroll
            for (int d = 0; d < 32; ++d) a += sQ[rr * 36 + d] * g_KE[t * 256 + h * 32 + d];
            sqe[rr * 2 + t] = a;
        }

        // ---- Q fragments (pre-rounded tf32) ----
        FragA af[4];
#pragma unroll
        for (int kt = 0; kt < 4; ++kt)
            wmma::load_matrix_sync(af[kt], &sQ[kt * 8], 36);

        // ---- SCORE: stream K chunks (dbuf -> one sync per chunk) ----
        const float4* gK = reinterpret_cast<const float4*>(g_K + h * 32768);
        float4 pf0, pf1, pf2, pf3;
        pf0 = __ldg(gK + tid);
        pf1 = __ldg(gK + tid + 256);
        pf2 = __ldg(gK + tid + 512);
        pf3 = __ldg(gK + tid + 768);

        for (int kc = 0; kc < 8; ++kc) {
            float* buf = sKV + (kc & 1) * CH_F;
            {
                int i0 = tid, i1 = tid + 256, i2 = tid + 512, i3 = tid + 768;
                *reinterpret_cast<float4*>(&buf[(i0 >> 3) * 36 + (i0 & 7) * 4]) = pf0;
                *reinterpret_cast<float4*>(&buf[(i1 >> 3) * 36 + (i1 & 7) * 4]) = pf1;
                *reinterpret_cast<float4*>(&buf[(i2 >> 3) * 36 + (i2 & 7) * 4]) = pf2;
                *reinterpret_cast<float4*>(&buf[(i3 >> 3) * 36 + (i3 & 7) * 4]) = pf3;
            }
            __syncthreads();
            if (kc < 7) {
                const float4* src = gK + (kc + 1) * 1024;
                pf0 = __ldg(src + tid);
                pf1 = __ldg(src + tid + 256);
                pf2 = __ldg(src + tid + 512);
                pf3 = __ldg(src + tid + 768);
            }
            FragC c0;
            wmma::fill_fragment(c0, 0.f);
#pragma unroll
            for (int kt = 0; kt < 4; ++kt) {
                FragBc bf;
                wmma::load_matrix_sync(bf, &buf[w * 16 * 36 + kt * 8], 36);
                wmma::mma_sync(c0, af[kt], bf, c0);
            }
            wmma::store_matrix_sync(&sS[kc * 128 + w * 16], c0, SS_LD, wmma::mem_row_major);
            // no trailing sync (double-buffered)
        }
        __syncthreads();   // all S written before softmax

        // ---- V chunk 0 prefetch ----
        const float4* gV = reinterpret_cast<const float4*>(g_V + h * 32768);
        pf0 = __ldg(gV + tid);
        pf1 = __ldg(gV + tid + 256);
        pf2 = __ldg(gV + tid + 512);
        pf3 = __ldg(gV + tid + 768);

        // ---- softmax: ONE pass, no max subtraction ----
        const unsigned aw0 = sAdj[row * 32 + c16 * 2 + 0];
        const unsigned aw1 = sAdj[row * 32 + c16 * 2 + 1];
        const unsigned tw0 = sTyp[row * 32 + c16 * 2 + 0];
        const unsigned tw1 = sTyp[row * 32 + c16 * 2 + 1];
        const float qe0 = sqe[row * 2], qe1 = sqe[row * 2 + 1];
        float* rowp = sS + row * SS_LD + c16 * 64;

        float rs = 0.f, rw = 0.f;
#pragma unroll
        for (int jj = 0; jj < 16; ++jj) {
            int j = (jj + c16) & 15;              // lane stagger
            float4 s = *reinterpret_cast<float4*>(&rowp[j * 4]);
            unsigned a = (j & 8) ? aw1 : aw0;
            unsigned t = (j & 8) ? tw1 : tw0;
            int bb = (j & 7) * 4;
            float p0 = ((a >> (bb + 0)) & 1u) ? __expf(s.x + (((t >> (bb + 0)) & 1u) ? qe1 : qe0)) : 0.f;
            float p1 = ((a >> (bb + 1)) & 1u) ? __expf(s.y + (((t >> (bb + 1)) & 1u) ? qe1 : qe0)) : 0.f;
            float p2 = ((a >> (bb + 2)) & 1u) ? __expf(s.z + (((t >> (bb + 2)) & 1u) ? qe1 : qe0)) : 0.f;
            float p3 = ((a >> (bb + 3)) & 1u) ? __expf(s.w + (((t >> (bb + 3)) & 1u) ? qe1 : qe0)) : 0.f;
            rs += p0 + p1 + p2 + p3;
            if ((t >> (bb + 0)) & 1u) rw += p0;
            if ((t >> (bb + 1)) & 1u) rw += p1;
            if ((t >> (bb + 2)) & 1u) rw += p2;
            if ((t >> (bb + 3)) & 1u) rw += p3;
            s.x = wmma::__float_to_tf32(p0);      // pre-round P for the PV MMA
            s.y = wmma::__float_to_tf32(p1);
            s.z = wmma::__float_to_tf32(p2);
            s.w = wmma::__float_to_tf32(p3);
            *reinterpret_cast<float4*>(&rowp[j * 4]) = s;
        }
#pragma unroll
        for (int m = 8; m; m >>= 1) {
            rs += __shfl_xor_sync(0xffffffffu, rs, m);
            rw += __shfl_xor_sync(0xffffffffu, rw, m);
        }
        if (c16 == 0) { srs[row] = rs; srw[row] = rw; }
        __syncthreads();

        // ---- AV: warp w owns kv slice [w*16, w*16+16) of each chunk ----
        FragC oc[2];
        wmma::fill_fragment(oc[0], 0.f);
        wmma::fill_fragment(oc[1], 0.f);

        for (int kc = 0; kc < 8; ++kc) {
            float* buf = sKV + (kc & 1) * CH_F;
            {
                int i0 = tid, i1 = tid + 256, i2 = tid + 512, i3 = tid + 768;
                *reinterpret_cast<float4*>(&buf[(i0 >> 3) * 36 + (i0 & 7) * 4]) = pf0;
                *reinterpret_cast<float4*>(&buf[(i1 >> 3) * 36 + (i1 & 7) * 4]) = pf1;
                *reinterpret_cast<float4*>(&buf[(i2 >> 3) * 36 + (i2 & 7) * 4]) = pf2;
                *reinterpret_cast<float4*>(&buf[(i3 >> 3) * 36 + (i3 & 7) * 4]) = pf3;
            }
            __syncthreads();
            if (kc < 7) {
                const float4* src = gV + (kc + 1) * 1024;
                pf0 = __ldg(src + tid);
                pf1 = __ldg(src + tid + 256);
                pf2 = __ldg(src + tid + 512);
                pf3 = __ldg(src + tid + 768);
            }
#pragma unroll
            for (int kt2 = 0; kt2 < 2; ++kt2) {
                int kb = w * 16 + kt2 * 8;
                FragA pa;
                wmma::load_matrix_sync(pa, &sS[kc * 128 + kb], SS_LD);
                FragBr vb0, vb1;
                wmma::load_matrix_sync(vb0, &buf[kb * 36 + 0], 36);
                wmma::load_matrix_sync(vb1, &buf[kb * 36 + 16], 36);
                wmma::mma_sync(oc[0], pa, vb0, oc[0]);
                wmma::mma_sync(oc[1], pa, vb1, oc[1]);
            }
            // no trailing sync (double-buffered; red-store safety: all warps
            // passed chunk 7's leading sync => finished chunk 6 = last buf0 read)
        }

        float* red = sKV;   // 8 * 576 = 4608 = CH_F (= buf0)
        wmma::store_matrix_sync(&red[w * 576 + 0],  oc[0], 36, wmma::mem_row_major);
        wmma::store_matrix_sync(&red[w * 576 + 16], oc[1], 36, wmma::mem_row_major);
        __syncthreads();

#pragma unroll
        for (int i = 0; i < 2; ++i) {
            int o = tid + i * 256;
            int r = o >> 5, d = o & 31;
            float v = 0.f;
#pragma unroll
            for (int ww = 0; ww < 8; ++ww) v += red[ww * 576 + r * 36 + d];
            float st = srs[r], w1s = srw[r];
            float inv = st > 0.f ? 1.f / st : 0.f;
            v = v * inv + (st - w1s) * inv * sVE[d] + w1s * inv * sVE[32 + d];
            g_AO[(b0 + r) * 256 + h * 32 + d] = v;
        }
        __syncthreads();   // job state (sQ/sS/red) settled before next job
    }
}

// ---------------------------------------------------------------------------
extern "C" void kernel_launch(void* const* d_in, const int* in_sizes, int n_in,
                              void* d_out, int out_size)
{
    const float* h_target = (const float*)d_in[0];
    const float* h_neigh  = (const float*)d_in[1];
    const int*   adjacency = (const int*)d_in[2];
    const int*   edge_types = (const int*)d_in[3];
    const float* Wq = (const float*)d_in[4];
    const float* bq = (const float*)d_in[5];
    const float* Wk = (const float*)d_in[6];
    const float* bk = (const float*)d_in[7];
    const float* Wv = (const float*)d_in[8];
    const float* bv = (const float*)d_in[9];
    const float* Wo = (const float*)d_in[10];
    const float* bo = (const float*)d_in[11];
    const float* E  = (const float*)d_in[12];
    float* out = (float*)d_out;

    const int attn_smem = SMEM_ATTN_F * 4;   // 109,824 B -> 2 CTAs/SM
    static int smem_set = 0;
    if (!smem_set) {
        cudaFuncSetAttribute(attn_kernel, cudaFuncAttributeMaxDynamicSharedMemorySize,
                             attn_smem);
        smem_set = 1;
    }

    prep_kernel<<<516, 256>>>(h_target, h_neigh, Wq, bq, Wk, bk, Wv, bv, E,
                              adjacency, edge_types);
    attn_kernel<<<ATTN_CTAS, 256, attn_smem>>>();
    proj_kernel<<<dim3(32, 4), 256>>>(Wo, bo, out);
}

// round 16
// speedup vs baseline: 1.4265x; 1.0565x over previous
#include <cuda_runtime.h>
#include <mma.h>

using namespace nvcuda;

// ---------------------------------------------------------------------------
// HGTransformerLayer — tf32 tensor-core, round 16 (= R12 attention verbatim,
// proj upgraded to 2xTF32).
//   k[b,n] = Kbase[n] + KE[t], v[b,n] = Vbase[n] + VE[t]  (t in {0,1})
//   scores = Q·Kbase^T + qe[row][t];  out = P·Vbase + w0·VE0 + w1·VE1
// GEMMs: smem-staged 32x64; QKV 1xTF32, proj 2xTF32 (A split, W rounded).
// Attention: 16 rows/CTA, 2 CTAs/SM, 512-CTA grid, single-pass no-max
// softmax, double-buffered K/V chunks.
// ---------------------------------------------------------------------------

#define SCALE_Q 0.17677669529663687f  // 1/sqrt(32)

__device__ float g_Q[1024 * 256];   // [h][b][32], scaled, tf32-rounded
__device__ float g_K[1024 * 256];   // [h][n][32], tf32-rounded
__device__ float g_V[1024 * 256];   // [h][n][32], tf32-rounded
__device__ float g_KE[2 * 256];
__device__ float g_VE[2 * 256];
__device__ float g_AO[1024 * 256];  // row-major [b][256]
__device__ unsigned g_mba2[1024 * 32];  // adjacency bits: [row][n/32]
__device__ unsigned g_mbt2[1024 * 32];  // edge-type bits

typedef wmma::fragment<wmma::matrix_a, 16, 16, 8, wmma::precision::tf32, wmma::row_major> FragA;
typedef wmma::fragment<wmma::matrix_b, 16, 16, 8, wmma::precision::tf32, wmma::col_major> FragBc;
typedef wmma::fragment<wmma::matrix_b, 16, 16, 8, wmma::precision::tf32, wmma::row_major> FragBr;
typedef wmma::fragment<wmma::accumulator, 16, 16, 8, float> FragC;

template <typename F>
__device__ __forceinline__ void to_tf32(F& f) {
#pragma unroll
    for (int i = 0; i < f.num_elements; ++i) f.x[i] = wmma::__float_to_tf32(f.x[i]);
}
template <typename F>
__device__ __forceinline__ void split_tf32(const F& raw, F& hi, F& lo) {
#pragma unroll
    for (int i = 0; i < raw.num_elements; ++i) {
        float h = wmma::__float_to_tf32(raw.x[i]);
        hi.x[i] = h;
        lo.x[i] = wmma::__float_to_tf32(raw.x[i] - h);
    }
}

// ---------------------------------------------------------------------------
// GEMM body: C[32x64 tile] = (A[.,256] @ W[256,256]^T + bias) * scale
// 256 threads, 8 warps (2 row x 4 col), warp tile 16x16, BK=16, smem dbuf.
// ACC2: 2xTF32 (split A only, round W); else single tf32 pass.
// ---------------------------------------------------------------------------
template <bool ACC2>
__device__ __forceinline__ void gemm_body(const float* __restrict__ A,
                                          const float* __restrict__ W,
                                          const float* __restrict__ bias,
                                          float* __restrict__ C, float scale,
                                          bool headmode, int m0, int n0)
{
    __shared__ float sA[2][32 * 20];
    __shared__ float sB[2][64 * 20];
    __shared__ float sEp[8 * 320];

    const int tid = threadIdx.x;
    const int warp = tid >> 5;
    const int wr = warp >> 2;
    const int wc = warp & 3;

    float4 pa, pb;
    if (tid < 128)
        pa = *reinterpret_cast<const float4*>(&A[(m0 + (tid >> 2)) * 256 + (tid & 3) * 4]);
    pb = *reinterpret_cast<const float4*>(&W[(n0 + (tid >> 2)) * 256 + (tid & 3) * 4]);

    FragC c;
    wmma::fill_fragment(c, 0.f);

    for (int s = 0; s < 16; ++s) {
        float* bufA = sA[s & 1];
        float* bufB = sB[s & 1];
        if (tid < 128)
            *reinterpret_cast<float4*>(&bufA[(tid >> 2) * 20 + (tid & 3) * 4]) = pa;
        *reinterpret_cast<float4*>(&bufB[(tid >> 2) * 20 + (tid & 3) * 4]) = pb;
        __syncthreads();
        if (s < 15) {
            int k0 = (s + 1) * 16;
            if (tid < 128)
                pa = *reinterpret_cast<const float4*>(&A[(m0 + (tid >> 2)) * 256 + k0 + (tid & 3) * 4]);
            pb = *reinterpret_cast<const float4*>(&W[(n0 + (tid >> 2)) * 256 + k0 + (tid & 3) * 4]);
        }
#pragma unroll
        for (int kt = 0; kt < 2; ++kt) {
            FragA araw;
            FragBc braw;
            wmma::load_matrix_sync(araw, &bufA[wr * 16 * 20 + kt * 8], 20);
            wmma::load_matrix_sync(braw, &bufB[wc * 16 * 20 + kt * 8], 20);
            if (ACC2) {
                FragA ahi, alo;
                split_tf32(araw, ahi, alo);
                to_tf32(braw);
                wmma::mma_sync(c, ahi, braw, c);
                wmma::mma_sync(c, alo, braw, c);
            } else {
                to_tf32(araw);
                to_tf32(braw);
                wmma::mma_sync(c, araw, braw, c);
            }
        }
    }
    __syncthreads();
    wmma::store_matrix_sync(&sEp[warp * 320], c, 20, wmma::mem_row_major);
    __syncthreads();

#pragma unroll
    for (int i = 0; i < 8; ++i) {
        int o = tid + i * 256;
        int lm = o >> 6, ln = o & 63;
        int wsrc = (lm >> 4) * 4 + (ln >> 4);
        float val = sEp[wsrc * 320 + (lm & 15) * 20 + (ln & 15)];
        int m = m0 + lm, n = n0 + ln;
        val = (val + __ldg(&bias[n])) * scale;
        if (headmode) {
            val = wmma::__float_to_tf32(val);
            C[(n >> 5) * 32768 + m * 32 + (n & 31)] = val;
        } else {
            C[m * 256 + n] = val;
        }
    }
}

// ---------------------------------------------------------------------------
// prep: [0,128) mask pack; [128,512) qkv GEMMs (1xTF32); [512,516) edge proj.
// ---------------------------------------------------------------------------
__global__ __launch_bounds__(256)
void prep_kernel(const float* __restrict__ hT, const float* __restrict__ hN,
                 const float* __restrict__ Wq, const float* __restrict__ bq,
                 const float* __restrict__ Wk, const float* __restrict__ bk,
                 const float* __restrict__ Wv, const float* __restrict__ bv,
                 const float* __restrict__ E,
                 const int* __restrict__ adj, const int* __restrict__ et)
{
    const int b = blockIdx.x;
    if (b < 128) {
        const int gw = b * 256 + threadIdx.x;
        const int4* ap = reinterpret_cast<const int4*>(adj) + gw * 8;
        const int4* tp = reinterpret_cast<const int4*>(et) + gw * 8;
        unsigned va = 0, vt = 0;
#pragma unroll
        for (int i = 0; i < 8; ++i) {
            int4 xa = __ldg(ap + i);
            int4 xt = __ldg(tp + i);
            va |= (unsigned)(xa.x != 0) << (i * 4 + 0);
            va |= (unsigned)(xa.y != 0) << (i * 4 + 1);
            va |= (unsigned)(xa.z != 0) << (i * 4 + 2);
            va |= (unsigned)(xa.w != 0) << (i * 4 + 3);
            vt |= (unsigned)(xt.x != 0) << (i * 4 + 0);
            vt |= (unsigned)(xt.y != 0) << (i * 4 + 1);
            vt |= (unsigned)(xt.z != 0) << (i * 4 + 2);
            vt |= (unsigned)(xt.w != 0) << (i * 4 + 3);
        }
        g_mba2[gw] = va;
        g_mbt2[gw] = vt;
    } else if (b < 512) {
        const int bb = b - 128;
        const int mat = bb >> 7;
        const int m0 = (bb & 31) * 32;
        const int n0 = ((bb >> 5) & 3) * 64;
        if (mat == 0)      gemm_body<false>(hT, Wq, bq, g_Q, SCALE_Q, true, m0, n0);
        else if (mat == 1) gemm_body<false>(hN, Wk, bk, g_K, 1.f, true, m0, n0);
        else               gemm_body<false>(hN, Wv, bv, g_V, 1.f, true, m0, n0);
    } else {
        const int bb = b - 512;
        const int t = bb & 1;
        const int isv = bb >> 1;
        const float* W = isv ? Wv : Wk;
        float* out = isv ? g_VE : g_KE;
        __shared__ float e[256];
        e[threadIdx.x] = E[t * 256 + threadIdx.x];
        __syncthreads();
        const int warp = threadIdx.x >> 5, lane = threadIdx.x & 31;
        for (int d = warp; d < 256; d += 8) {
            float acc = 0.f;
            for (int k = lane; k < 256; k += 32) acc += e[k] * W[d * 256 + k];
#pragma unroll
            for (int m = 16; m; m >>= 1) acc += __shfl_xor_sync(0xffffffffu, acc, m);
            if (lane == 0) out[t * 256 + d] = acc;
        }
    }
}

__global__ __launch_bounds__(256)
void proj_kernel(const float* __restrict__ Wo, const float* __restrict__ bo,
                 float* __restrict__ out)
{
    gemm_body<true>(g_AO, Wo, bo, out, 1.f, false, blockIdx.x * 32, blockIdx.y * 64);
}

// ---------------------------------------------------------------------------
// Attention (R12 verbatim): grid (64 rowblocks, 8 heads), 256 thr, 2 CTAs/SM.
// 16 rows/CTA. S[16x1032] smem; K/V 128-kv double-buffered chunks.
// Softmax: single pass (no max), P tf32-rounded on write.
// ---------------------------------------------------------------------------
#define SS_LD 1032
#define CH_F (128 * 36)
#define SMEM_ATTN_F (16 * SS_LD + 2 * CH_F + 16 * 36 + 32 + 64 + 16 + 16 + 1024)

__global__ __launch_bounds__(256, 2)
void attn_kernel()
{
    extern __shared__ float sm[];
    float* sS  = sm;                          // 16512
    float* sKV = sS + 16 * SS_LD;             // 9216 (dbuf; later AV reduce)
    float* sQ  = sKV + 2 * CH_F;              // 576
    float* sqe = sQ + 16 * 36;                // 32
    float* sVE = sqe + 32;                    // 64
    float* srs = sVE + 64;                    // 16
    float* srw = srs + 16;                    // 16
    unsigned* sAdj = (unsigned*)(srw + 16);   // 512
    unsigned* sTyp = sAdj + 512;              // 512

    const int tid = threadIdx.x;
    const int h = blockIdx.y;
    const int b0 = blockIdx.x * 16;
    const int w = tid >> 5;

    // ---- stage Q, masks, VE ----
#pragma unroll
    for (int j = 0; j < 2; ++j) {
        int idx = tid + j * 256;
        sQ[(idx >> 5) * 36 + (idx & 31)] = g_Q[h * 32768 + (b0 + (idx >> 5)) * 32 + (idx & 31)];
    }
#pragma unroll
    for (int j = 0; j < 2; ++j) {
        int idx = tid + j * 256;
        sAdj[idx] = g_mba2[(b0 + (idx >> 5)) * 32 + (idx & 31)];
        sTyp[idx] = g_mbt2[(b0 + (idx >> 5)) * 32 + (idx & 31)];
    }
    if (tid < 64) sVE[tid] = g_VE[(tid >> 5) * 256 + h * 32 + (tid & 31)];
    __syncthreads();

    // qe[row][t] = Q[row].KE[t]
    if (tid < 32) {
        int row = tid >> 1, t = tid & 1;
        float a = 0.f;
#pragma unroll
        for (int d = 0; d < 32; ++d) a += sQ[row * 36 + d] * g_KE[t * 256 + h * 32 + d];
        sqe[row * 2 + t] = a;
    }

    // ---- Q fragments (pre-rounded tf32) ----
    FragA af[4];
#pragma unroll
    for (int kt = 0; kt < 4; ++kt)
        wmma::load_matrix_sync(af[kt], &sQ[kt * 8], 36);

    // ---- SCORE: stream K chunks (dbuf -> one sync per chunk) ----
    const float4* gK = reinterpret_cast<const float4*>(g_K + h * 32768);
    float4 pf0, pf1, pf2, pf3;
    pf0 = __ldg(gK + tid);
    pf1 = __ldg(gK + tid + 256);
    pf2 = __ldg(gK + tid + 512);
    pf3 = __ldg(gK + tid + 768);

    for (int kc = 0; kc < 8; ++kc) {
        float* buf = sKV + (kc & 1) * CH_F;
        {
            int i0 = tid, i1 = tid + 256, i2 = tid + 512, i3 = tid + 768;
            *reinterpret_cast<float4*>(&buf[(i0 >> 3) * 36 + (i0 & 7) * 4]) = pf0;
            *reinterpret_cast<float4*>(&buf[(i1 >> 3) * 36 + (i1 & 7) * 4]) = pf1;
            *reinterpret_cast<float4*>(&buf[(i2 >> 3) * 36 + (i2 & 7) * 4]) = pf2;
            *reinterpret_cast<float4*>(&buf[(i3 >> 3) * 36 + (i3 & 7) * 4]) = pf3;
        }
        __syncthreads();
        if (kc < 7) {
            const float4* src = gK + (kc + 1) * 1024;
            pf0 = __ldg(src + tid);
            pf1 = __ldg(src + tid + 256);
            pf2 = __ldg(src + tid + 512);
            pf3 = __ldg(src + tid + 768);
        }
        FragC c0;
        wmma::fill_fragment(c0, 0.f);
#pragma unroll
        for (int kt = 0; kt < 4; ++kt) {
            FragBc bf;
            wmma::load_matrix_sync(bf, &buf[w * 16 * 36 + kt * 8], 36);
            wmma::mma_sync(c0, af[kt], bf, c0);
        }
        wmma::store_matrix_sync(&sS[kc * 128 + w * 16], c0, SS_LD, wmma::mem_row_major);
        // no trailing sync (double-buffered)
    }
    __syncthreads();   // all S written before softmax

    // ---- V chunk 0 prefetch ----
    const float4* gV = reinterpret_cast<const float4*>(g_V + h * 32768);
    pf0 = __ldg(gV + tid);
    pf1 = __ldg(gV + tid + 256);
    pf2 = __ldg(gV + tid + 512);
    pf3 = __ldg(gV + tid + 768);

    // ---- softmax: ONE pass, no max subtraction ----
    const int row = tid >> 4, c16 = tid & 15;
    const unsigned aw0 = sAdj[row * 32 + c16 * 2 + 0];
    const unsigned aw1 = sAdj[row * 32 + c16 * 2 + 1];
    const unsigned tw0 = sTyp[row * 32 + c16 * 2 + 0];
    const unsigned tw1 = sTyp[row * 32 + c16 * 2 + 1];
    const float qe0 = sqe[row * 2], qe1 = sqe[row * 2 + 1];
    float* rowp = sS + row * SS_LD + c16 * 64;

    float rs = 0.f, rw = 0.f;
#pragma unroll
    for (int jj = 0; jj < 16; ++jj) {
        int j = (jj + c16) & 15;              // lane stagger
        float4 s = *reinterpret_cast<float4*>(&rowp[j * 4]);
        unsigned a = (j & 8) ? aw1 : aw0;
        unsigned t = (j & 8) ? tw1 : tw0;
        int bb = (j & 7) * 4;
        float p0 = ((a >> (bb + 0)) & 1u) ? __expf(s.x + (((t >> (bb + 0)) & 1u) ? qe1 : qe0)) : 0.f;
        float p1 = ((a >> (bb + 1)) & 1u) ? __expf(s.y + (((t >> (bb + 1)) & 1u) ? qe1 : qe0)) : 0.f;
        float p2 = ((a >> (bb + 2)) & 1u) ? __expf(s.z + (((t >> (bb + 2)) & 1u) ? qe1 : qe0)) : 0.f;
        float p3 = ((a >> (bb + 3)) & 1u) ? __expf(s.w + (((t >> (bb + 3)) & 1u) ? qe1 : qe0)) : 0.f;
        rs += p0 + p1 + p2 + p3;
        if ((t >> (bb + 0)) & 1u) rw += p0;
        if ((t >> (bb + 1)) & 1u) rw += p1;
        if ((t >> (bb + 2)) & 1u) rw += p2;
        if ((t >> (bb + 3)) & 1u) rw += p3;
        s.x = wmma::__float_to_tf32(p0);      // pre-round P for the PV MMA
        s.y = wmma::__float_to_tf32(p1);
        s.z = wmma::__float_to_tf32(p2);
        s.w = wmma::__float_to_tf32(p3);
        *reinterpret_cast<float4*>(&rowp[j * 4]) = s;
    }
#pragma unroll
    for (int m = 8; m; m >>= 1) {
        rs += __shfl_xor_sync(0xffffffffu, rs, m);
        rw += __shfl_xor_sync(0xffffffffu, rw, m);
    }
    if (c16 == 0) { srs[row] = rs; srw[row] = rw; }
    __syncthreads();

    // ---- AV: warp w owns kv slice [w*16, w*16+16) of each chunk ----
    FragC oc[2];
    wmma::fill_fragment(oc[0], 0.f);
    wmma::fill_fragment(oc[1], 0.f);

    for (int kc = 0; kc < 8; ++kc) {
        float* buf = sKV + (kc & 1) * CH_F;
        {
            int i0 = tid, i1 = tid + 256, i2 = tid + 512, i3 = tid + 768;
            *reinterpret_cast<float4*>(&buf[(i0 >> 3) * 36 + (i0 & 7) * 4]) = pf0;
            *reinterpret_cast<float4*>(&buf[(i1 >> 3) * 36 + (i1 & 7) * 4]) = pf1;
            *reinterpret_cast<float4*>(&buf[(i2 >> 3) * 36 + (i2 & 7) * 4]) = pf2;
            *reinterpret_cast<float4*>(&buf[(i3 >> 3) * 36 + (i3 & 7) * 4]) = pf3;
        }
        __syncthreads();
        if (kc < 7) {
            const float4* src = gV + (kc + 1) * 1024;
            pf0 = __ldg(src + tid);
            pf1 = __ldg(src + tid + 256);
            pf2 = __ldg(src + tid + 512);
            pf3 = __ldg(src + tid + 768);
        }
#pragma unroll
        for (int kt2 = 0; kt2 < 2; ++kt2) {
            int kb = w * 16 + kt2 * 8;
            FragA pa;
            wmma::load_matrix_sync(pa, &sS[kc * 128 + kb], SS_LD);
            FragBr vb0, vb1;
            wmma::load_matrix_sync(vb0, &buf[kb * 36 + 0], 36);
            wmma::load_matrix_sync(vb1, &buf[kb * 36 + 16], 36);
            wmma::mma_sync(oc[0], pa, vb0, oc[0]);
            wmma::mma_sync(oc[1], pa, vb1, oc[1]);
        }
        // no trailing sync (double-buffered; red-store safety argued below)
    }

    // red = buf0 region; last buf0 reads were chunk 6 (all warps passed
    // chunk 7's leading sync, hence finished chunk 6); chunk-7 readers use buf1.
    float* red = sKV;   // 8 * 576 = 4608 = CH_F
    wmma::store_matrix_sync(&red[w * 576 + 0],  oc[0], 36, wmma::mem_row_major);
    wmma::store_matrix_sync(&red[w * 576 + 16], oc[1], 36, wmma::mem_row_major);
    __syncthreads();

#pragma unroll
    for (int i = 0; i < 2; ++i) {
        int o = tid + i * 256;
        int r = o >> 5, d = o & 31;
        float v = 0.f;
#pragma unroll
        for (int ww = 0; ww < 8; ++ww) v += red[ww * 576 + r * 36 + d];
        float st = srs[r], w1s = srw[r];
        float inv = st > 0.f ? 1.f / st : 0.f;
        v = v * inv + (st - w1s) * inv * sVE[d] + w1s * inv * sVE[32 + d];
        g_AO[(b0 + r) * 256 + h * 32 + d] = v;
    }
}

// ---------------------------------------------------------------------------
extern "C" void kernel_launch(void* const* d_in, const int* in_sizes, int n_in,
                              void* d_out, int out_size)
{
    const float* h_target = (const float*)d_in[0];
    const float* h_neigh  = (const float*)d_in[1];
    const int*   adjacency = (const int*)d_in[2];
    const int*   edge_types = (const int*)d_in[3];
    const float* Wq = (const float*)d_in[4];
    const float* bq = (const float*)d_in[5];
    const float* Wk = (const float*)d_in[6];
    const float* bk = (const float*)d_in[7];
    const float* Wv = (const float*)d_in[8];
    const float* bv = (const float*)d_in[9];
    const float* Wo = (const float*)d_in[10];
    const float* bo = (const float*)d_in[11];
    const float* E  = (const float*)d_in[12];
    float* out = (float*)d_out;

    const int attn_smem = SMEM_ATTN_F * 4;   // 109,824 B -> 2 CTAs/SM
    static int smem_set = 0;
    if (!smem_set) {
        cudaFuncSetAttribute(attn_kernel, cudaFuncAttributeMaxDynamicSharedMemorySize,
                             attn_smem);
        smem_set = 1;
    }

    prep_kernel<<<516, 256>>>(h_target, h_neigh, Wq, bq, Wk, bk, Wv, bv, E,
                              adjacency, edge_types);
    attn_kernel<<<dim3(64, 8), 256, attn_smem>>>();
    proj_kernel<<<dim3(32, 4), 256>>>(Wo, bo, out);
}

// round 17
// speedup vs baseline: 1.5629x; 1.0956x over previous
#include <cuda_runtime.h>
#include <mma.h>

using namespace nvcuda;

// ---------------------------------------------------------------------------
// HGTransformerLayer — tf32 tensor-core, round 17.
//   k[b,n] = Kbase[n] + KE[t], v[b,n] = Vbase[n] + VE[t]  (t in {0,1})
//   scores = Q·Kbase^T + qe[row][t];  out = P·Vbase + w0·VE0 + w1·VE1
// GEMMs: BK=32 (8 barriers instead of 16); QKV 1xTF32, proj 2xTF32.
// All redundant __float_to_tf32 removed: tf32 MMA HW ignores low mantissa
// bits, so explicit cvt (RN) is only a rounding-mode nicety vs truncation.
// Attention: R12/R16 design (16 rows/CTA, 2 CTAs/SM, single-pass no-max
// softmax, double-buffered K/V chunks), minus the P-rounding cvts.
// ---------------------------------------------------------------------------

#define SCALE_Q 0.17677669529663687f  // 1/sqrt(32)

__device__ float g_Q[1024 * 256];   // [h][b][32], scaled
__device__ float g_K[1024 * 256];   // [h][n][32]
__device__ float g_V[1024 * 256];   // [h][n][32]
__device__ float g_KE[2 * 256];
__device__ float g_VE[2 * 256];
__device__ float g_AO[1024 * 256];  // row-major [b][256]
__device__ unsigned g_mba2[1024 * 32];  // adjacency bits: [row][n/32]
__device__ unsigned g_mbt2[1024 * 32];  // edge-type bits

typedef wmma::fragment<wmma::matrix_a, 16, 16, 8, wmma::precision::tf32, wmma::row_major> FragA;
typedef wmma::fragment<wmma::matrix_b, 16, 16, 8, wmma::precision::tf32, wmma::col_major> FragBc;
typedef wmma::fragment<wmma::matrix_b, 16, 16, 8, wmma::precision::tf32, wmma::row_major> FragBr;
typedef wmma::fragment<wmma::accumulator, 16, 16, 8, float> FragC;

template <typename F>
__device__ __forceinline__ void split_tf32(const F& raw, F& hi, F& lo) {
#pragma unroll
    for (int i = 0; i < raw.num_elements; ++i) {
        float h = wmma::__float_to_tf32(raw.x[i]);   // exact hi needed for lo
        hi.x[i] = h;
        lo.x[i] = raw.x[i] - h;                      // HW truncates lo's tail
    }
}

// ---------------------------------------------------------------------------
// GEMM body: C[32x64 tile] = (A[.,256] @ W[256,256]^T + bias) * scale
// 256 threads, 8 warps (2 row x 4 col), warp tile 16x16, BK=32, smem dbuf.
// ACC2: 2xTF32 (split A, raw W); else raw single-pass (HW-truncated tf32).
// ---------------------------------------------------------------------------
template <bool ACC2>
__device__ __forceinline__ void gemm_body(const float* __restrict__ A,
                                          const float* __restrict__ W,
                                          const float* __restrict__ bias,
                                          float* __restrict__ C, float scale,
                                          bool headmode, int m0, int n0)
{
    __shared__ float sA[2][32 * 36];
    __shared__ float sB[2][64 * 36];
    __shared__ float sEp[8 * 320];

    const int tid = threadIdx.x;
    const int warp = tid >> 5;
    const int wr = warp >> 2;        // 0..1 row tile
    const int wc = warp & 3;         // 0..3 col tile
    const int r8 = tid >> 3;         // 0..31
    const int k8 = tid & 7;          // 0..7 (float4 group within 32 k)

    float4 pa, pb0, pb1;
    pa  = *reinterpret_cast<const float4*>(&A[(m0 + r8) * 256 + k8 * 4]);
    pb0 = *reinterpret_cast<const float4*>(&W[(n0 + r8) * 256 + k8 * 4]);
    pb1 = *reinterpret_cast<const float4*>(&W[(n0 + 32 + r8) * 256 + k8 * 4]);

    FragC c;
    wmma::fill_fragment(c, 0.f);

    for (int s = 0; s < 8; ++s) {
        float* bufA = sA[s & 1];
        float* bufB = sB[s & 1];
        *reinterpret_cast<float4*>(&bufA[r8 * 36 + k8 * 4]) = pa;
        *reinterpret_cast<float4*>(&bufB[r8 * 36 + k8 * 4]) = pb0;
        *reinterpret_cast<float4*>(&bufB[(32 + r8) * 36 + k8 * 4]) = pb1;
        __syncthreads();
        if (s < 7) {
            int k0 = (s + 1) * 32;
            pa  = *reinterpret_cast<const float4*>(&A[(m0 + r8) * 256 + k0 + k8 * 4]);
            pb0 = *reinterpret_cast<const float4*>(&W[(n0 + r8) * 256 + k0 + k8 * 4]);
            pb1 = *reinterpret_cast<const float4*>(&W[(n0 + 32 + r8) * 256 + k0 + k8 * 4]);
        }
#pragma unroll
        for (int kt = 0; kt < 4; ++kt) {
            FragA araw;
            FragBc braw;
            wmma::load_matrix_sync(araw, &bufA[wr * 16 * 36 + kt * 8], 36);
            wmma::load_matrix_sync(braw, &bufB[wc * 16 * 36 + kt * 8], 36);
            if (ACC2) {
                FragA ahi, alo;
                split_tf32(araw, ahi, alo);
                wmma::mma_sync(c, ahi, braw, c);
                wmma::mma_sync(c, alo, braw, c);
            } else {
                wmma::mma_sync(c, araw, braw, c);   // HW truncates to tf32
            }
        }
        // no trailing sync: next iteration writes the other buffer
    }
    __syncthreads();
    wmma::store_matrix_sync(&sEp[warp * 320], c, 20, wmma::mem_row_major);
    __syncthreads();

#pragma unroll
    for (int i = 0; i < 8; ++i) {
        int o = tid + i * 256;
        int lm = o >> 6, ln = o & 63;
        int wsrc = (lm >> 4) * 4 + (ln >> 4);
        float val = sEp[wsrc * 320 + (lm & 15) * 20 + (ln & 15)];
        int m = m0 + lm, n = n0 + ln;
        val = (val + __ldg(&bias[n])) * scale;
        if (headmode) C[(n >> 5) * 32768 + m * 32 + (n & 31)] = val;
        else          C[m * 256 + n] = val;
    }
}

// ---------------------------------------------------------------------------
// prep: [0,128) mask pack; [128,512) qkv GEMMs (1xTF32); [512,516) edge proj.
// ---------------------------------------------------------------------------
__global__ __launch_bounds__(256)
void prep_kernel(const float* __restrict__ hT, const float* __restrict__ hN,
                 const float* __restrict__ Wq, const float* __restrict__ bq,
                 const float* __restrict__ Wk, const float* __restrict__ bk,
                 const float* __restrict__ Wv, const float* __restrict__ bv,
                 const float* __restrict__ E,
                 const int* __restrict__ adj, const int* __restrict__ et)
{
    const int b = blockIdx.x;
    if (b < 128) {
        const int gw = b * 256 + threadIdx.x;
        const int4* ap = reinterpret_cast<const int4*>(adj) + gw * 8;
        const int4* tp = reinterpret_cast<const int4*>(et) + gw * 8;
        unsigned va = 0, vt = 0;
#pragma unroll
        for (int i = 0; i < 8; ++i) {
            int4 xa = __ldg(ap + i);
            int4 xt = __ldg(tp + i);
            va |= (unsigned)(xa.x != 0) << (i * 4 + 0);
            va |= (unsigned)(xa.y != 0) << (i * 4 + 1);
            va |= (unsigned)(xa.z != 0) << (i * 4 + 2);
            va |= (unsigned)(xa.w != 0) << (i * 4 + 3);
            vt |= (unsigned)(xt.x != 0) << (i * 4 + 0);
            vt |= (unsigned)(xt.y != 0) << (i * 4 + 1);
            vt |= (unsigned)(xt.z != 0) << (i * 4 + 2);
            vt |= (unsigned)(xt.w != 0) << (i * 4 + 3);
        }
        g_mba2[gw] = va;
        g_mbt2[gw] = vt;
    } else if (b < 512) {
        const int bb = b - 128;
        const int mat = bb >> 7;
        const int m0 = (bb & 31) * 32;
        const int n0 = ((bb >> 5) & 3) * 64;
        if (mat == 0)      gemm_body<false>(hT, Wq, bq, g_Q, SCALE_Q, true, m0, n0);
        else if (mat == 1) gemm_body<false>(hN, Wk, bk, g_K, 1.f, true, m0, n0);
        else               gemm_body<false>(hN, Wv, bv, g_V, 1.f, true, m0, n0);
    } else {
        const int bb = b - 512;
        const int t = bb & 1;
        const int isv = bb >> 1;
        const float* W = isv ? Wv : Wk;
        float* out = isv ? g_VE : g_KE;
        __shared__ float e[256];
        e[threadIdx.x] = E[t * 256 + threadIdx.x];
        __syncthreads();
        const int warp = threadIdx.x >> 5, lane = threadIdx.x & 31;
        for (int d = warp; d < 256; d += 8) {
            float acc = 0.f;
            for (int k = lane; k < 256; k += 32) acc += e[k] * W[d * 256 + k];
#pragma unroll
            for (int m = 16; m; m >>= 1) acc += __shfl_xor_sync(0xffffffffu, acc, m);
            if (lane == 0) out[t * 256 + d] = acc;
        }
    }
}

__global__ __launch_bounds__(256)
void proj_kernel(const float* __restrict__ Wo, const float* __restrict__ bo,
                 float* __restrict__ out)
{
    gemm_body<true>(g_AO, Wo, bo, out, 1.f, false, blockIdx.x * 32, blockIdx.y * 64);
}

// ---------------------------------------------------------------------------
// Attention: grid (64 rowblocks, 8 heads), 256 thr / 8 warps, 2 CTAs/SM.
// 16 rows/CTA. S[16x1032] smem; K/V 128-kv double-buffered chunks.
// Softmax: single pass (no max); P stored raw (tf32 MMA truncates in HW).
// ---------------------------------------------------------------------------
#define SS_LD 1032
#define CH_F (128 * 36)
#define SMEM_ATTN_F (16 * SS_LD + 2 * CH_F + 16 * 36 + 32 + 64 + 16 + 16 + 1024)

__global__ __launch_bounds__(256, 2)
void attn_kernel()
{
    extern __shared__ float sm[];
    float* sS  = sm;                          // 16512
    float* sKV = sS + 16 * SS_LD;             // 9216 (dbuf; later AV reduce)
    float* sQ  = sKV + 2 * CH_F;              // 576
    float* sqe = sQ + 16 * 36;                // 32
    float* sVE = sqe + 32;                    // 64
    float* srs = sVE + 64;                    // 16
    float* srw = srs + 16;                    // 16
    unsigned* sAdj = (unsigned*)(srw + 16);   // 512
    unsigned* sTyp = sAdj + 512;              // 512

    const int tid = threadIdx.x;
    const int h = blockIdx.y;
    const int b0 = blockIdx.x * 16;
    const int w = tid >> 5;

    // ---- stage Q, masks, VE ----
#pragma unroll
    for (int j = 0; j < 2; ++j) {
        int idx = tid + j * 256;
        sQ[(idx >> 5) * 36 + (idx & 31)] = g_Q[h * 32768 + (b0 + (idx >> 5)) * 32 + (idx & 31)];
    }
#pragma unroll
    for (int j = 0; j < 2; ++j) {
        int idx = tid + j * 256;
        sAdj[idx] = g_mba2[(b0 + (idx >> 5)) * 32 + (idx & 31)];
        sTyp[idx] = g_mbt2[(b0 + (idx >> 5)) * 32 + (idx & 31)];
    }
    if (tid < 64) sVE[tid] = g_VE[(tid >> 5) * 256 + h * 32 + (tid & 31)];
    __syncthreads();

    // qe[row][t] = Q[row].KE[t]
    if (tid < 32) {
        int row = tid >> 1, t = tid & 1;
        float a = 0.f;
#pragma unroll
        for (int d = 0; d < 32; ++d) a += sQ[row * 36 + d] * g_KE[t * 256 + h * 32 + d];
        sqe[row * 2 + t] = a;
    }

    // ---- Q fragments (HW truncates to tf32 in the MMA) ----
    FragA af[4];
#pragma unroll
    for (int kt = 0; kt < 4; ++kt)
        wmma::load_matrix_sync(af[kt], &sQ[kt * 8], 36);

    // ---- SCORE: stream K chunks (dbuf -> one sync per chunk) ----
    const float4* gK = reinterpret_cast<const float4*>(g_K + h * 32768);
    float4 pf0, pf1, pf2, pf3;
    pf0 = __ldg(gK + tid);
    pf1 = __ldg(gK + tid + 256);
    pf2 = __ldg(gK + tid + 512);
    pf3 = __ldg(gK + tid + 768);

    for (int kc = 0; kc < 8; ++kc) {
        float* buf = sKV + (kc & 1) * CH_F;
        {
            int i0 = tid, i1 = tid + 256, i2 = tid + 512, i3 = tid + 768;
            *reinterpret_cast<float4*>(&buf[(i0 >> 3) * 36 + (i0 & 7) * 4]) = pf0;
            *reinterpret_cast<float4*>(&buf[(i1 >> 3) * 36 + (i1 & 7) * 4]) = pf1;
            *reinterpret_cast<float4*>(&buf[(i2 >> 3) * 36 + (i2 & 7) * 4]) = pf2;
            *reinterpret_cast<float4*>(&buf[(i3 >> 3) * 36 + (i3 & 7) * 4]) = pf3;
        }
        __syncthreads();
        if (kc < 7) {
            const float4* src = gK + (kc + 1) * 1024;
            pf0 = __ldg(src + tid);
            pf1 = __ldg(src + tid + 256);
            pf2 = __ldg(src + tid + 512);
            pf3 = __ldg(src + tid + 768);
        }
        FragC c0;
        wmma::fill_fragment(c0, 0.f);
#pragma unroll
        for (int kt = 0; kt < 4; ++kt) {
            FragBc bf;
            wmma::load_matrix_sync(bf, &buf[w * 16 * 36 + kt * 8], 36);
            wmma::mma_sync(c0, af[kt], bf, c0);
        }
        wmma::store_matrix_sync(&sS[kc * 128 + w * 16], c0, SS_LD, wmma::mem_row_major);
        // no trailing sync (double-buffered)
    }
    __syncthreads();   // all S written before softmax

    // ---- V chunk 0 prefetch ----
    const float4* gV = reinterpret_cast<const float4*>(g_V + h * 32768);
    pf0 = __ldg(gV + tid);
    pf1 = __ldg(gV + tid + 256);
    pf2 = __ldg(gV + tid + 512);
    pf3 = __ldg(gV + tid + 768);

    // ---- softmax: ONE pass, no max subtraction, raw P (HW truncates) ----
    const int row = tid >> 4, c16 = tid & 15;
    const unsigned aw0 = sAdj[row * 32 + c16 * 2 + 0];
    const unsigned aw1 = sAdj[row * 32 + c16 * 2 + 1];
    const unsigned tw0 = sTyp[row * 32 + c16 * 2 + 0];
    const unsigned tw1 = sTyp[row * 32 + c16 * 2 + 1];
    const float qe0 = sqe[row * 2], qe1 = sqe[row * 2 + 1];
    float* rowp = sS + row * SS_LD + c16 * 64;

    float rs = 0.f, rw = 0.f;
#pragma unroll
    for (int jj = 0; jj < 16; ++jj) {
        int j = (jj + c16) & 15;              // lane stagger
        float4 s = *reinterpret_cast<float4*>(&rowp[j * 4]);
        unsigned a = (j & 8) ? aw1 : aw0;
        unsigned t = (j & 8) ? tw1 : tw0;
        int bb = (j & 7) * 4;
        float p0 = ((a >> (bb + 0)) & 1u) ? __expf(s.x + (((t >> (bb + 0)) & 1u) ? qe1 : qe0)) : 0.f;
        float p1 = ((a >> (bb + 1)) & 1u) ? __expf(s.y + (((t >> (bb + 1)) & 1u) ? qe1 : qe0)) : 0.f;
        float p2 = ((a >> (bb + 2)) & 1u) ? __expf(s.z + (((t >> (bb + 2)) & 1u) ? qe1 : qe0)) : 0.f;
        float p3 = ((a >> (bb + 3)) & 1u) ? __expf(s.w + (((t >> (bb + 3)) & 1u) ? qe1 : qe0)) : 0.f;
        rs += p0 + p1 + p2 + p3;
        if ((t >> (bb + 0)) & 1u) rw += p0;
        if ((t >> (bb + 1)) & 1u) rw += p1;
        if ((t >> (bb + 2)) & 1u) rw += p2;
        if ((t >> (bb + 3)) & 1u) rw += p3;
        s.x = p0; s.y = p1; s.z = p2; s.w = p3;
        *reinterpret_cast<float4*>(&rowp[j * 4]) = s;
    }
#pragma unroll
    for (int m = 8; m; m >>= 1) {
        rs += __shfl_xor_sync(0xffffffffu, rs, m);
        rw += __shfl_xor_sync(0xffffffffu, rw, m);
    }
    if (c16 == 0) { srs[row] = rs; srw[row] = rw; }
    __syncthreads();

    // ---- AV: warp w owns kv slice [w*16, w*16+16) of each chunk ----
    FragC oc[2];
    wmma::fill_fragment(oc[0], 0.f);
    wmma::fill_fragment(oc[1], 0.f);

    for (int kc = 0; kc < 8; ++kc) {
        float* buf = sKV + (kc & 1) * CH_F;
        {
            int i0 = tid, i1 = tid + 256, i2 = tid + 512, i3 = tid + 768;
            *reinterpret_cast<float4*>(&buf[(i0 >> 3) * 36 + (i0 & 7) * 4]) = pf0;
            *reinterpret_cast<float4*>(&buf[(i1 >> 3) * 36 + (i1 & 7) * 4]) = pf1;
            *reinterpret_cast<float4*>(&buf[(i2 >> 3) * 36 + (i2 & 7) * 4]) = pf2;
            *reinterpret_cast<float4*>(&buf[(i3 >> 3) * 36 + (i3 & 7) * 4]) = pf3;
        }
        __syncthreads();
        if (kc < 7) {
            const float4* src = gV + (kc + 1) * 1024;
            pf0 = __ldg(src + tid);
            pf1 = __ldg(src + tid + 256);
            pf2 = __ldg(src + tid + 512);
            pf3 = __ldg(src + tid + 768);
        }
#pragma unroll
        for (int kt2 = 0; kt2 < 2; ++kt2) {
            int kb = w * 16 + kt2 * 8;
            FragA pa;
            wmma::load_matrix_sync(pa, &sS[kc * 128 + kb], SS_LD);
            FragBr vb0, vb1;
            wmma::load_matrix_sync(vb0, &buf[kb * 36 + 0], 36);
            wmma::load_matrix_sync(vb1, &buf[kb * 36 + 16], 36);
            wmma::mma_sync(oc[0], pa, vb0, oc[0]);
            wmma::mma_sync(oc[1], pa, vb1, oc[1]);
        }
        // no trailing sync (double-buffered; red-store safety argued below)
    }

    // red = buf0 region; last buf0 reads were chunk 6 (all warps passed
    // chunk 7's leading sync, hence finished chunk 6); chunk-7 readers use buf1.
    float* red = sKV;   // 8 * 576 = 4608 = CH_F
    wmma::store_matrix_sync(&red[w * 576 + 0],  oc[0], 36, wmma::mem_row_major);
    wmma::store_matrix_sync(&red[w * 576 + 16], oc[1], 36, wmma::mem_row_major);
    __syncthreads();

#pragma unroll
    for (int i = 0; i < 2; ++i) {
        int o = tid + i * 256;
        int r = o >> 5, d = o & 31;
        float v = 0.f;
#pragma unroll
        for (int ww = 0; ww < 8; ++ww) v += red[ww * 576 + r * 36 + d];
        float st = srs[r], w1s = srw[r];
        float inv = st > 0.f ? 1.f / st : 0.f;
        v = v * inv + (st - w1s) * inv * sVE[d] + w1s * inv * sVE[32 + d];
        g_AO[(b0 + r) * 256 + h * 32 + d] = v;
    }
}

// ---------------------------------------------------------------------------
extern "C" void kernel_launch(void* const* d_in, const int* in_sizes, int n_in,
                              void* d_out, int out_size)
{
    const float* h_target = (const float*)d_in[0];
    const float* h_neigh  = (const float*)d_in[1];
    const int*   adjacency = (const int*)d_in[2];
    const int*   edge_types = (const int*)d_in[3];
    const float* Wq = (const float*)d_in[4];
    const float* bq = (const float*)d_in[5];
    const float* Wk = (const float*)d_in[6];
    const float* bk = (const float*)d_in[7];
    const float* Wv = (const float*)d_in[8];
    const float* bv = (const float*)d_in[9];
    const float* Wo = (const float*)d_in[10];
    const float* bo = (const float*)d_in[11];
    const float* E  = (const float*)d_in[12];
    float* out = (float*)d_out;

    const int attn_smem = SMEM_ATTN_F * 4;   // 109,824 B -> 2 CTAs/SM
    static int smem_set = 0;
    if (!smem_set) {
        cudaFuncSetAttribute(attn_kernel, cudaFuncAttributeMaxDynamicSharedMemorySize,
                             attn_smem);
        smem_set = 1;
    }

    prep_kernel<<<516, 256>>>(h_target, h_neigh, Wq, bq, Wk, bk, Wv, bv, E,
                              adjacency, edge_types);
    attn_kernel<<<dim3(64, 8), 256, attn_smem>>>();
    proj_kernel<<<dim3(32, 4), 256>>>(Wo, bo, out);
}